// round 10
// baseline (speedup 1.0000x reference)
#include <cuda_runtime.h>
#include <cuda_bf16.h>
#include <cstdint>
#include <math.h>

// Problem constants
#define B_    16
#define N_    2048
#define D_    128
#define H_    8
#define F_    65
#define ROWS_ 32768
#define N1_   2080       // q,k: 2 regions * 8 heads * 130 (re/im interleaved u=2f+p)
#define N1P_  2176       // 17 n-tiles of 128
#define NK_   1040
#define SCALE_ (1.0f/65.0f)
#define EQ_   8

// ---------------- scratch (static device, no allocation) ----------------
__device__ __nv_bfloat16 g_Xhi[(size_t)ROWS_ * D_];
__device__ __nv_bfloat16 g_Xlo[(size_t)ROWS_ * D_];
__device__ __nv_bfloat16 g_W1T_hi[N1P_ * D_];
__device__ __nv_bfloat16 g_W1T_lo[N1P_ * D_];
__device__ float g_W1v[D_ * NK_];
__device__ float g_Mout[H_ * 2 * F_ * D_];       // [h][p][x][o]
__device__ float g_aq[(size_t)ROWS_ * H_ * F_];
__device__ float g_ak[(size_t)ROWS_ * H_ * F_];
__device__ float g_attp[B_ * H_ * EQ_ * F_ * F_];
__device__ float g_C[B_ * NK_ * D_];             // [b][k][o]
__device__ __nv_bfloat16 g_DThi[B_ * D_ * D_];
__device__ __nv_bfloat16 g_DTlo[B_ * D_ * D_];

// ---------------- helpers ----------------
__device__ __forceinline__ uint32_t smem_u32(const void* p) {
    uint32_t a;
    asm("{ .reg .u64 t; cvta.to.shared.u64 t, %1; cvt.u32.u64 %0, t; }" : "=r"(a) : "l"(p));
    return a;
}
__device__ __forceinline__ void ldsm_x4(uint32_t* r, uint32_t addr) {
    asm volatile("ldmatrix.sync.aligned.m8n8.x4.shared.b16 {%0,%1,%2,%3}, [%4];"
                 : "=r"(r[0]), "=r"(r[1]), "=r"(r[2]), "=r"(r[3]) : "r"(addr));
}
__device__ __forceinline__ void mma16816(float* c, const uint32_t* a, const uint32_t* b) {
    asm volatile("mma.sync.aligned.m16n8k16.row.col.f32.bf16.bf16.f32 "
                 "{%0,%1,%2,%3}, {%4,%5,%6,%7}, {%8,%9}, {%0,%1,%2,%3};"
                 : "+f"(c[0]), "+f"(c[1]), "+f"(c[2]), "+f"(c[3])
                 : "r"(a[0]), "r"(a[1]), "r"(a[2]), "r"(a[3]), "r"(b[0]), "r"(b[1]));
}
#define FMA_F32X2(d, a, b) \
    asm("fma.rn.f32x2 %0, %1, %2, %0;" : "+l"(d) : "l"(a), "l"(b))
__device__ __forceinline__ uint32_t pack_bf(__nv_bfloat16 a, __nv_bfloat16 b) {
    __nv_bfloat162 p = __halves2bfloat162(a, b);
    return *reinterpret_cast<uint32_t*>(&p);
}
// swizzled offsets: 128B rows (64 bf16) and 64B rows (32 bf16)
__device__ __forceinline__ uint32_t swz64(int row, int colbyte) {
    return (uint32_t)(row * 128 + (colbyte ^ ((row & 7) << 4)));
}
__device__ __forceinline__ uint32_t swz32(int row, int colbyte) {
    return (uint32_t)(row * 64 + (colbyte ^ ((row & 3) << 4)));
}
__device__ __forceinline__ void cp16(uint32_t dst, const void* src) {
    asm volatile("cp.async.cg.shared.global [%0], [%1], 16;" :: "r"(dst), "l"(src));
}
__device__ __forceinline__ void cp_commit() { asm volatile("cp.async.commit_group;"); }
__device__ __forceinline__ void cp_wait0() { asm volatile("cp.async.wait_group 0;" ::: "memory"); }
__device__ __forceinline__ void cp_wait1() { asm volatile("cp.async.wait_group 1;" ::: "memory"); }

// ---------------- merged prep ----------------
#define PREP_SPLIT  4096
#define PREP_W1     1088
#define PREP_W1V    520
#define PREP_MOUT   520
#define PREP_TOTAL  (PREP_SPLIT + PREP_W1 + PREP_W1V + PREP_MOUT)

__global__ void __launch_bounds__(256) prep_kernel(const float* __restrict__ X,
                                                   const float* __restrict__ w_qkv,
                                                   const float* __restrict__ w_out) {
    __shared__ float cs[128], sn[128];
    int tid = threadIdx.x;
    int blk = blockIdx.x;
    if (blk < PREP_SPLIT) {
        size_t i = (size_t)blk * 256 + tid;
        float4 v = ((const float4*)X)[i];
        __nv_bfloat16 h0 = __float2bfloat16(v.x), h1 = __float2bfloat16(v.y);
        __nv_bfloat16 h2 = __float2bfloat16(v.z), h3 = __float2bfloat16(v.w);
        ((uint2*)g_Xhi)[i] = make_uint2(pack_bf(h0, h1), pack_bf(h2, h3));
        ((uint2*)g_Xlo)[i] = make_uint2(
            pack_bf(__float2bfloat16(v.x - __bfloat162float(h0)),
                    __float2bfloat16(v.y - __bfloat162float(h1))),
            pack_bf(__float2bfloat16(v.z - __bfloat162float(h2)),
                    __float2bfloat16(v.w - __bfloat162float(h3))));
        return;
    }
    if (tid < 128) {
        float ang = (float)tid / 64.0f;
        cs[tid] = cospif(ang);
        sn[tid] = sinpif(ang);
    }
    __syncthreads();
    blk -= PREP_SPLIT;
    if (blk < PREP_W1) {
        int idx = blk * 256 + tid;
        int d = idx / N1P_, c = idx - d * N1P_;
        float acc = 0.f;
        if (c < N1_) {
            int region = (c >= 1040) ? 1 : 0;
            int cc = c - region * 1040;
            int hd = cc / 130;
            int u = cc - hd * 130;
            int f = u >> 1;
            const float* w = w_qkv + (size_t)d * 3072 + region * 1024 + hd * 128;
            if ((u & 1) == 0) {
                #pragma unroll 8
                for (int dd = 0; dd < 128; dd++) acc += w[dd] * cs[(f * dd) & 127];
            } else {
                #pragma unroll 8
                for (int dd = 0; dd < 128; dd++) acc -= w[dd] * sn[(f * dd) & 127];
            }
            acc *= SCALE_;
        }
        __nv_bfloat16 hi = __float2bfloat16(acc);
        g_W1T_hi[c * 128 + d] = hi;
        g_W1T_lo[c * 128 + d] = __float2bfloat16(acc - __bfloat162float(hi));
        return;
    }
    blk -= PREP_W1;
    if (blk < PREP_W1V) {
        int idx = blk * 256 + tid;
        int d = idx / NK_, k = idx - d * NK_;
        int hd = k / 130;
        int u = k - hd * 130;
        int f = u >> 1;
        const float* w = w_qkv + (size_t)d * 3072 + 2048 + hd * 128;
        float acc = 0.f;
        if ((u & 1) == 0) {
            #pragma unroll 8
            for (int dd = 0; dd < 128; dd++) acc += w[dd] * cs[(f * dd) & 127];
        } else {
            #pragma unroll 8
            for (int dd = 0; dd < 128; dd++) acc -= w[dd] * sn[(f * dd) & 127];
        }
        g_W1v[idx] = acc;
        return;
    }
    blk -= PREP_W1V;
    {
        int idx = blk * 256 + tid;
        int o = idx & 127;
        int r = idx >> 7;
        int x = r % 65;
        int hp = r / 65;
        int p = hp & 1, hd = hp >> 1;
        float acc = 0.f;
        if (p == 0) {
            #pragma unroll 8
            for (int t2 = 0; t2 < 128; t2++)
                acc += cs[(x * t2) & 127] * w_out[(size_t)(hd * 128 + t2) * 128 + o];
            acc *= ((x == 0 || x == 64) ? 1.0f : 2.0f) / 128.0f;
        } else if (x != 0 && x != 64) {
            #pragma unroll 8
            for (int t2 = 0; t2 < 128; t2++)
                acc -= sn[(x * t2) & 127] * w_out[(size_t)(hd * 128 + t2) * 128 + o];
            acc *= 2.0f / 128.0f;
        }
        g_Mout[idx] = acc;
    }
}

// ---------------- GEMM1: m128 x n128, 256 thr, 2 CTAs/SM ----------------
// SMEM: Ahi 32K @0 (2 x 16K K-chunks of 64), Alo @32768;
//       B stages @65536: 2 x (Bhi 8K + Blo 8K), K-chunks of 32 (swz32 rows)
#define G1_SMEM 98304

__device__ __forceinline__ void g1_load_b(uint32_t bs, int bn, int k0, int tid) {
    #pragma unroll
    for (int u = tid; u < 512; u += 256) {
        int r = u >> 2, cb = (u & 3) * 16;
        uint32_t d = swz32(r, cb);
        size_t src = (size_t)(bn + r) * 256 + (size_t)k0 * 2 + cb;
        cp16(bs + d,        (const char*)g_W1T_hi + src);
        cp16(bs + 8192 + d, (const char*)g_W1T_lo + src);
    }
}

// fused 3-product sweep over one 32-wide K-chunk (2 k-steps of 16)
__device__ __forceinline__ void mma_chunk32(uint32_t sb, int ach, int acb0, uint32_t bs,
                                            int lane, int wm, int wn, float c[2][8][4]) {
    uint32_t sAhi = sb + ach * 16384;
    uint32_t sAlo = sb + 32768 + ach * 16384;
    uint32_t sBhi = bs, sBlo = bs + 8192;
    int hw = (lane >> 4) * 16;
    int arow = wm * 32 + (lane & 15);
    #pragma unroll
    for (int ks = 0; ks < 2; ks++) {
        int acolb = acb0 + ks * 32 + hw;
        int bcolb = ks * 32 + hw;
        uint32_t ahi[2][4];
        #pragma unroll
        for (int tm = 0; tm < 2; tm++)
            ldsm_x4(ahi[tm], sAhi + swz64(arow + tm * 16, acolb));
        uint32_t bhi[8][2];
        #pragma unroll
        for (int ng = 0; ng < 4; ng++) {
            int n = wn * 64 + ng * 16 + (lane & 15);
            uint32_t q[4];
            ldsm_x4(q, sBhi + swz32(n, bcolb));
            bhi[2 * ng][0] = q[0]; bhi[2 * ng + 1][0] = q[1];
            bhi[2 * ng][1] = q[2]; bhi[2 * ng + 1][1] = q[3];
        }
        #pragma unroll
        for (int tm = 0; tm < 2; tm++)
            #pragma unroll
            for (int tn = 0; tn < 8; tn++)
                mma16816(c[tm][tn], ahi[tm], bhi[tn]);
        uint32_t blo[8][2];
        #pragma unroll
        for (int ng = 0; ng < 4; ng++) {
            int n = wn * 64 + ng * 16 + (lane & 15);
            uint32_t q[4];
            ldsm_x4(q, sBlo + swz32(n, bcolb));
            blo[2 * ng][0] = q[0]; blo[2 * ng + 1][0] = q[1];
            blo[2 * ng][1] = q[2]; blo[2 * ng + 1][1] = q[3];
        }
        #pragma unroll
        for (int tm = 0; tm < 2; tm++)
            #pragma unroll
            for (int tn = 0; tn < 8; tn++)
                mma16816(c[tm][tn], ahi[tm], blo[tn]);
        uint32_t alo[2][4];
        #pragma unroll
        for (int tm = 0; tm < 2; tm++)
            ldsm_x4(alo[tm], sAlo + swz64(arow + tm * 16, acolb));
        #pragma unroll
        for (int tm = 0; tm < 2; tm++)
            #pragma unroll
            for (int tn = 0; tn < 8; tn++)
                mma16816(c[tm][tn], alo[tm], bhi[tn]);
    }
}

__global__ void __launch_bounds__(256, 2) gemm1_tc() {
    extern __shared__ char smem[];
    uint32_t sb = smem_u32(smem);
    int tid = threadIdx.x;
    int lane = tid & 31, wid = tid >> 5;
    int wm = wid & 3, wn = wid >> 2;      // 4 x 2 warps over 128 x 128
    int bm = blockIdx.y * 128, bn = blockIdx.x * 128;

    // A resident (whole K=128), hi/lo
    #pragma unroll
    for (int u = tid; u < 2048; u += 256) {
        int r = u >> 4, seg = u & 15;
        int ch = seg >> 3, cb = (seg & 7) * 16;
        uint32_t d = ch * 16384 + swz64(r, cb);
        size_t src = (size_t)(bm + r) * 256 + ch * 128 + cb;
        cp16(sb + d,         (const char*)g_Xhi + src);
        cp16(sb + 32768 + d, (const char*)g_Xlo + src);
    }
    g1_load_b(sb + 65536, bn, 0, tid);
    cp_commit();                                   // G0: A + B0
    g1_load_b(sb + 65536 + 16384, bn, 32, tid);
    cp_commit();                                   // G1: B1

    float c[2][8][4];
    #pragma unroll
    for (int i = 0; i < 2; i++)
        #pragma unroll
        for (int j = 0; j < 8; j++)
            #pragma unroll
            for (int k = 0; k < 4; k++) c[i][j][k] = 0.f;

    for (int kc = 0; kc < 4; kc++) {
        if (kc == 3) cp_wait0(); else cp_wait1();
        __syncthreads();
        uint32_t bs = sb + 65536 + (kc & 1) * 16384;
        mma_chunk32(sb, kc >> 1, (kc & 1) * 64, bs, lane, wm, wn, c);
        __syncthreads();
        if (kc + 2 < 4) { g1_load_b(bs, bn, (kc + 2) * 32, tid); cp_commit(); }
    }

    // epilogue: |q|,|k|
    int g = lane >> 2, cp2 = (lane & 3) * 2;
    #pragma unroll
    for (int tn = 0; tn < 8; tn++) {
        int col = bn + wn * 64 + tn * 8 + cp2;   // even
        if (col >= N1_) continue;
        int region = (col >= 1040) ? 1 : 0;
        int cc = col - region * 1040;
        int hd = cc / 130;
        int uu = cc - hd * 130;
        int f = uu >> 1;
        float* base = region ? g_ak : g_aq;
        #pragma unroll
        for (int tm = 0; tm < 2; tm++)
            #pragma unroll
            for (int hf = 0; hf < 2; hf++) {
                size_t row = (size_t)bm + wm * 32 + tm * 16 + hf * 8 + g;
                float re = c[tm][tn][hf * 2], im = c[tm][tn][hf * 2 + 1];
                base[(row * 8 + hd) * 65 + f] = sqrtf(re * re + im * im);
            }
    }
}

// ---------------- att partial: packed f32x2 FMA, stride-66 smem ----------------
__global__ void __launch_bounds__(256) att_partial_kernel() {
    __shared__ float aqs[65 * 66];
    __shared__ float aks[65 * 66];
    int bh = blockIdx.y;
    int b = bh >> 3, h = bh & 7;
    int chunk = blockIdx.x;
    int tid = threadIdx.x;
    int tx = tid & 15, ty = tid >> 4;
    int xs[5], ys[5];
    #pragma unroll
    for (int i = 0; i < 5; i++) {
        int x = tx + 16 * i; xs[i] = (x < 65) ? x : 0;
        int y = ty + 16 * i; ys[i] = (y < 65) ? y : 0;
    }
    unsigned long long acc2[5][5];
    #pragma unroll
    for (int i = 0; i < 5; i++)
        #pragma unroll
        for (int j = 0; j < 5; j++) acc2[i][j] = 0ull;   // packed (0.f, 0.f)

    int ebase = chunk * (2048 / EQ_);
    for (int e0 = ebase; e0 < ebase + 2048 / EQ_; e0 += 64) {
        for (int idx = tid; idx < 4160; idx += 256) {
            int r = idx / 65, f = idx - r * 65;
            size_t gidx = ((size_t)((b * 2048 + e0 + r) * 8 + h)) * 65 + f;
            aqs[f * 66 + r] = g_aq[gidx];
            aks[f * 66 + r] = g_ak[gidx];
        }
        __syncthreads();
        #pragma unroll 4
        for (int e2 = 0; e2 < 64; e2 += 2) {
            unsigned long long av[5], bv[5];
            #pragma unroll
            for (int i = 0; i < 5; i++)
                av[i] = *(const unsigned long long*)&aqs[xs[i] * 66 + e2];
            #pragma unroll
            for (int j = 0; j < 5; j++)
                bv[j] = *(const unsigned long long*)&aks[ys[j] * 66 + e2];
            #pragma unroll
            for (int i = 0; i < 5; i++)
                #pragma unroll
                for (int j = 0; j < 5; j++)
                    FMA_F32X2(acc2[i][j], av[i], bv[j]);
        }
        __syncthreads();
    }
    float* dst = g_attp + (size_t)(bh * EQ_ + chunk) * 4225;
    #pragma unroll
    for (int i = 0; i < 5; i++) {
        int x = tx + 16 * i;
        if (x < 65)
            #pragma unroll
            for (int j = 0; j < 5; j++) {
                int y = ty + 16 * j;
                if (y < 65) {
                    float lo = __uint_as_float((uint32_t)(acc2[i][j] & 0xffffffffull));
                    float hi = __uint_as_float((uint32_t)(acc2[i][j] >> 32));
                    dst[x * 65 + y] = lo + hi;
                }
            }
    }
}

// ---------------- merged softmax + build_C (one CTA per bh) ----------------
__global__ void __launch_bounds__(256) softmax_buildc_kernel() {
    extern __shared__ float csm[];
    float* att_s = csm;            // 4225
    float* mout_s = csm + 4225;    // 8320
    int bh = blockIdx.x;
    int b = bh >> 3, hd = bh & 7;
    int tid = threadIdx.x;
    const float* p0 = g_attp + (size_t)(bh * EQ_) * 4225;
    for (int idx = tid; idx < 4225; idx += 256) {
        float s = 0.f;
        #pragma unroll
        for (int q = 0; q < EQ_; q++) s += p0[q * 4225 + idx];
        att_s[idx] = s;
    }
    __syncthreads();
    int warp = tid >> 5, lane = tid & 31;
    for (int x = warp; x < 65; x += 8) {
        float m = -3.4e38f;
        for (int y = lane; y < 65; y += 32) m = fmaxf(m, att_s[x * 65 + y]);
        #pragma unroll
        for (int o = 16; o; o >>= 1) m = fmaxf(m, __shfl_xor_sync(0xffffffffu, m, o));
        float s = 0.f;
        for (int y = lane; y < 65; y += 32) {
            float v = expf(att_s[x * 65 + y] - m);
            att_s[x * 65 + y] = v;
            s += v;
        }
        #pragma unroll
        for (int o = 16; o; o >>= 1) s += __shfl_xor_sync(0xffffffffu, s, o);
        float inv = 1.0f / s;
        for (int y = lane; y < 65; y += 32) att_s[x * 65 + y] *= inv;
    }
    __syncthreads();
    #pragma unroll
    for (int p = 0; p < 2; p++) {
        const float* msrc = g_Mout + (size_t)(hd * 2 + p) * 8320;
        for (int idx = tid; idx < 8320; idx += 256) mout_s[idx] = msrc[idx];
        __syncthreads();
        for (int idx = tid; idx < 8320; idx += 256) {
            int o = idx / 65, y = idx - o * 65;
            float acc = 0.f;
            #pragma unroll 5
            for (int x = 0; x < 65; x++)
                acc += att_s[x * 65 + y] * mout_s[x * 128 + o];
            int k = hd * 130 + 2 * y + p;
            g_C[((size_t)b * NK_ + k) * 128 + o] = acc;
        }
        __syncthreads();
    }
}

// ---------------- build D_b = W1v @ C_b, split to DT hi/lo ----------------
__global__ void __launch_bounds__(256) build_d_kernel() {
    __shared__ float Wvs[128 * 65];
    __shared__ float Cs[65 * 32];
    int b = blockIdx.x;
    int o0 = blockIdx.y * 32;
    int tid = threadIdx.x;
    int ol = tid & 31, dg = tid >> 5;
    float acc[16];
    #pragma unroll
    for (int i = 0; i < 16; i++) acc[i] = 0.f;

    for (int k0 = 0; k0 < NK_; k0 += 65) {
        __syncthreads();
        for (int u = tid; u < 8320; u += 256) {
            int d = u / 65, kk = u - d * 65;
            Wvs[u] = g_W1v[(size_t)d * NK_ + k0 + kk];
        }
        for (int u = tid; u < 2080; u += 256) {
            int kk = u >> 5, oo = u & 31;
            Cs[u] = g_C[((size_t)b * NK_ + k0 + kk) * 128 + o0 + oo];
        }
        __syncthreads();
        #pragma unroll 5
        for (int kk = 0; kk < 65; kk++) {
            float cv = Cs[kk * 32 + ol];
            #pragma unroll
            for (int i = 0; i < 16; i++)
                acc[i] += Wvs[(dg + 8 * i) * 65 + kk] * cv;
        }
    }
    #pragma unroll
    for (int i = 0; i < 16; i++) {
        int d = dg + 8 * i;
        __nv_bfloat16 hi = __float2bfloat16(acc[i]);
        size_t off = ((size_t)b * 128 + o0 + ol) * 128 + d;
        g_DThi[off] = hi;
        g_DTlo[off] = __float2bfloat16(acc[i] - __bfloat162float(hi));
    }
}

// ---------------- final GEMM: out = X @ D_b + bias (m256, K=128, load-once) ----------------
#define FG_AHI 0
#define FG_ALO 65536
#define FG_BHI 131072
#define FG_BLO 163840
#define FG_TOT 196608

// fused 3-product sweep over one resident 64-wide K-chunk (swz64 rows), warp grid 8x2
__device__ __forceinline__ void mma_chunk64(uint32_t sAhi, uint32_t sAlo,
                                            uint32_t sBhi, uint32_t sBlo,
                                            int lane, int wm, int wn, float c[2][8][4]) {
    #pragma unroll
    for (int ks = 0; ks < 4; ks++) {
        int colb = ks * 32 + (lane >> 4) * 16;
        int ar = wm * 32 + (lane & 15);
        uint32_t ahi[2][4];
        #pragma unroll
        for (int tm = 0; tm < 2; tm++)
            ldsm_x4(ahi[tm], sAhi + swz64(ar + tm * 16, colb));
        uint32_t bhi[8][2];
        #pragma unroll
        for (int ng = 0; ng < 4; ng++) {
            int n = wn * 64 + ng * 16 + (lane & 15);
            uint32_t q[4];
            ldsm_x4(q, sBhi + swz64(n, colb));
            bhi[2 * ng][0] = q[0]; bhi[2 * ng + 1][0] = q[1];
            bhi[2 * ng][1] = q[2]; bhi[2 * ng + 1][1] = q[3];
        }
        #pragma unroll
        for (int tm = 0; tm < 2; tm++)
            #pragma unroll
            for (int tn = 0; tn < 8; tn++)
                mma16816(c[tm][tn], ahi[tm], bhi[tn]);
        uint32_t blo[8][2];
        #pragma unroll
        for (int ng = 0; ng < 4; ng++) {
            int n = wn * 64 + ng * 16 + (lane & 15);
            uint32_t q[4];
            ldsm_x4(q, sBlo + swz64(n, colb));
            blo[2 * ng][0] = q[0]; blo[2 * ng + 1][0] = q[1];
            blo[2 * ng][1] = q[2]; blo[2 * ng + 1][1] = q[3];
        }
        #pragma unroll
        for (int tm = 0; tm < 2; tm++)
            #pragma unroll
            for (int tn = 0; tn < 8; tn++)
                mma16816(c[tm][tn], ahi[tm], blo[tn]);
        uint32_t alo[2][4];
        #pragma unroll
        for (int tm = 0; tm < 2; tm++)
            ldsm_x4(alo[tm], sAlo + swz64(ar + tm * 16, colb));
        #pragma unroll
        for (int tm = 0; tm < 2; tm++)
            #pragma unroll
            for (int tn = 0; tn < 8; tn++)
                mma16816(c[tm][tn], alo[tm], bhi[tn]);
    }
}

__global__ void __launch_bounds__(512, 1) final_gemm(float* __restrict__ out,
                                                     const float* __restrict__ bias) {
    extern __shared__ char smem[];
    uint32_t sb = smem_u32(smem);
    int tid = threadIdx.x;
    int lane = tid & 31, wid = tid >> 5;
    int wm = wid & 7, wn = wid >> 3;
    int bm = blockIdx.x * 256;
    int b = bm >> 11;

    #pragma unroll
    for (int u = tid; u < 4096; u += 512) {
        int r = u >> 4, seg = u & 15;
        int ch = seg >> 3, cb = (seg & 7) * 16;
        uint32_t d = ch * 32768 + swz64(r, cb);
        size_t src = (size_t)(bm + r) * 256 + ch * 128 + cb;
        cp16(sb + FG_AHI + d, (const char*)g_Xhi + src);
        cp16(sb + FG_ALO + d, (const char*)g_Xlo + src);
    }
    #pragma unroll
    for (int u = tid; u < 2048; u += 512) {
        int r = u >> 4, seg = u & 15;
        int ch = seg >> 3, cb = (seg & 7) * 16;
        uint32_t d = ch * 16384 + swz64(r, cb);
        size_t src = ((size_t)(b * 128 + r)) * 256 + ch * 128 + cb;
        cp16(sb + FG_BHI + d, (const char*)g_DThi + src);
        cp16(sb + FG_BLO + d, (const char*)g_DTlo + src);
    }
    cp_commit();
    cp_wait0();
    __syncthreads();

    float c[2][8][4];
    #pragma unroll
    for (int i = 0; i < 2; i++)
        #pragma unroll
        for (int j = 0; j < 8; j++)
            #pragma unroll
            for (int k = 0; k < 4; k++) c[i][j][k] = 0.f;

    #pragma unroll
    for (int ch = 0; ch < 2; ch++)
        mma_chunk64(sb + FG_AHI + ch * 32768, sb + FG_ALO + ch * 32768,
                    sb + FG_BHI + ch * 16384, sb + FG_BLO + ch * 16384,
                    lane, wm, wn, c);

    int g = lane >> 2, cp2 = (lane & 3) * 2;
    #pragma unroll
    for (int tm = 0; tm < 2; tm++)
        #pragma unroll
        for (int hf = 0; hf < 2; hf++) {
            size_t row = (size_t)bm + wm * 32 + tm * 16 + hf * 8 + g;
            float* dst = out + row * 128;
            #pragma unroll
            for (int tn = 0; tn < 8; tn++) {
                int col = wn * 64 + tn * 8 + cp2;
                float2 bv = *(const float2*)(bias + col);
                *(float2*)(dst + col) = make_float2(c[tm][tn][hf * 2] + bv.x,
                                                    c[tm][tn][hf * 2 + 1] + bv.y);
            }
        }
}

// ---------------- launch ----------------
extern "C" void kernel_launch(void* const* d_in, const int* in_sizes, int n_in,
                              void* d_out, int out_size) {
    const float* x     = (const float*)d_in[0];
    const float* w_qkv = (const float*)d_in[1];
    const float* w_out = (const float*)d_in[2];
    const float* b_out = (const float*)d_in[3];
    float* out = (float*)d_out;

    cudaFuncSetAttribute(gemm1_tc, cudaFuncAttributeMaxDynamicSharedMemorySize, G1_SMEM);
    cudaFuncSetAttribute(final_gemm, cudaFuncAttributeMaxDynamicSharedMemorySize, FG_TOT);
    cudaFuncSetAttribute(softmax_buildc_kernel, cudaFuncAttributeMaxDynamicSharedMemorySize,
                         (4225 + 8320) * 4);

    prep_kernel<<<PREP_TOTAL, 256>>>(x, w_qkv, w_out);
    gemm1_tc<<<dim3(N1P_ / 128, ROWS_ / 128), 256, G1_SMEM>>>();
    att_partial_kernel<<<dim3(EQ_, B_ * H_), 256>>>();
    softmax_buildc_kernel<<<B_ * H_, 256, (4225 + 8320) * 4>>>();
    build_d_kernel<<<dim3(B_, 4), 256>>>();
    final_gemm<<<ROWS_ / 256, 512, FG_TOT>>>(out, b_out);
}

// round 11
// speedup vs baseline: 1.4964x; 1.4964x over previous
#include <cuda_runtime.h>
#include <cuda_bf16.h>
#include <cstdint>
#include <math.h>

// Problem constants
#define B_    16
#define N_    2048
#define D_    128
#define H_    8
#define F_    65
#define ROWS_ 32768
#define N1_   2080       // q,k: 2 regions * 8 heads * 130 (re/im interleaved u=2f+p)
#define N1P_  2176       // 17 n-tiles of 128
#define NK_   1040
#define SCALE_ (1.0f/65.0f)
#define EQ_   8

// ---------------- scratch (static device, no allocation) ----------------
__device__ __nv_bfloat16 g_Xhi[(size_t)ROWS_ * D_];
__device__ __nv_bfloat16 g_Xlo[(size_t)ROWS_ * D_];
__device__ __nv_bfloat16 g_W1T_hi[N1P_ * D_];
__device__ __nv_bfloat16 g_W1T_lo[N1P_ * D_];
__device__ float g_W1v[D_ * NK_];
__device__ float g_Mout[H_ * 2 * F_ * D_];       // [h][p][x][o]
__device__ float g_aq[(size_t)B_ * H_ * F_ * N_]; // [bh][f][e]
__device__ float g_ak[(size_t)B_ * H_ * F_ * N_];
__device__ float g_attp[B_ * H_ * EQ_ * F_ * F_];
__device__ float g_att[B_ * H_ * F_ * F_];
__device__ float g_C[B_ * NK_ * D_];             // [b][k][o]
__device__ __nv_bfloat16 g_DThi[B_ * D_ * D_];
__device__ __nv_bfloat16 g_DTlo[B_ * D_ * D_];

// ---------------- helpers ----------------
__device__ __forceinline__ uint32_t smem_u32(const void* p) {
    uint32_t a;
    asm("{ .reg .u64 t; cvta.to.shared.u64 t, %1; cvt.u32.u64 %0, t; }" : "=r"(a) : "l"(p));
    return a;
}
__device__ __forceinline__ void ldsm_x4(uint32_t* r, uint32_t addr) {
    asm volatile("ldmatrix.sync.aligned.m8n8.x4.shared.b16 {%0,%1,%2,%3}, [%4];"
                 : "=r"(r[0]), "=r"(r[1]), "=r"(r[2]), "=r"(r[3]) : "r"(addr));
}
__device__ __forceinline__ void mma16816(float* c, const uint32_t* a, const uint32_t* b) {
    asm volatile("mma.sync.aligned.m16n8k16.row.col.f32.bf16.bf16.f32 "
                 "{%0,%1,%2,%3}, {%4,%5,%6,%7}, {%8,%9}, {%0,%1,%2,%3};"
                 : "+f"(c[0]), "+f"(c[1]), "+f"(c[2]), "+f"(c[3])
                 : "r"(a[0]), "r"(a[1]), "r"(a[2]), "r"(a[3]), "r"(b[0]), "r"(b[1]));
}
__device__ __forceinline__ uint32_t pack_bf(__nv_bfloat16 a, __nv_bfloat16 b) {
    __nv_bfloat162 p = __halves2bfloat162(a, b);
    return *reinterpret_cast<uint32_t*>(&p);
}
// swizzled offset within a [rows][64 bf16] tile (row = 128 bytes)
__device__ __forceinline__ uint32_t swz64(int row, int colbyte) {
    return (uint32_t)(row * 128 + (colbyte ^ ((row & 7) << 4)));
}
__device__ __forceinline__ void cp16(uint32_t dst, const void* src) {
    asm volatile("cp.async.cg.shared.global [%0], [%1], 16;" :: "r"(dst), "l"(src));
}
__device__ __forceinline__ void cp_commit() { asm volatile("cp.async.commit_group;"); }
__device__ __forceinline__ void cp_wait0() { asm volatile("cp.async.wait_group 0;" ::: "memory"); }
__device__ __forceinline__ void cp_wait1() { asm volatile("cp.async.wait_group 1;" ::: "memory"); }

// fused 3-product sweep over one resident [*x64] K-chunk (4 k-steps).
// Per k-step: 12 ldsm feed 48 mma.
__device__ __forceinline__ void mma_chunk64(uint32_t sAhi, uint32_t sAlo,
                                            uint32_t sBhi, uint32_t sBlo,
                                            int lane, int wm, int wn, float c[2][8][4]) {
    #pragma unroll
    for (int ks = 0; ks < 4; ks++) {
        int colb = ks * 32 + (lane >> 4) * 16;
        int ar = wm * 32 + (lane & 15);
        uint32_t ahi[2][4], alo[2][4];
        #pragma unroll
        for (int tm = 0; tm < 2; tm++)
            ldsm_x4(ahi[tm], sAhi + swz64(ar + tm * 16, colb));
        uint32_t bhi[8][2], blo[8][2];
        #pragma unroll
        for (int ng = 0; ng < 4; ng++) {
            int n = wn * 64 + ng * 16 + (lane & 15);
            uint32_t q[4];
            ldsm_x4(q, sBhi + swz64(n, colb));
            bhi[2 * ng][0] = q[0]; bhi[2 * ng + 1][0] = q[1];
            bhi[2 * ng][1] = q[2]; bhi[2 * ng + 1][1] = q[3];
        }
        #pragma unroll
        for (int tm = 0; tm < 2; tm++)
            #pragma unroll
            for (int tn = 0; tn < 8; tn++)
                mma16816(c[tm][tn], ahi[tm], bhi[tn]);
        #pragma unroll
        for (int ng = 0; ng < 4; ng++) {
            int n = wn * 64 + ng * 16 + (lane & 15);
            uint32_t q[4];
            ldsm_x4(q, sBlo + swz64(n, colb));
            blo[2 * ng][0] = q[0]; blo[2 * ng + 1][0] = q[1];
            blo[2 * ng][1] = q[2]; blo[2 * ng + 1][1] = q[3];
        }
        #pragma unroll
        for (int tm = 0; tm < 2; tm++)
            #pragma unroll
            for (int tn = 0; tn < 8; tn++)
                mma16816(c[tm][tn], ahi[tm], blo[tn]);
        #pragma unroll
        for (int tm = 0; tm < 2; tm++)
            ldsm_x4(alo[tm], sAlo + swz64(ar + tm * 16, colb));
        #pragma unroll
        for (int tm = 0; tm < 2; tm++)
            #pragma unroll
            for (int tn = 0; tn < 8; tn++)
                mma16816(c[tm][tn], alo[tm], bhi[tn]);
    }
}

// ---------------- merged prep ----------------
#define PREP_SPLIT  4096
#define PREP_W1     1088
#define PREP_W1V    520
#define PREP_MOUT   520
#define PREP_TOTAL  (PREP_SPLIT + PREP_W1 + PREP_W1V + PREP_MOUT)

__global__ void __launch_bounds__(256) prep_kernel(const float* __restrict__ X,
                                                   const float* __restrict__ w_qkv,
                                                   const float* __restrict__ w_out) {
    __shared__ float cs[128], sn[128];
    int tid = threadIdx.x;
    int blk = blockIdx.x;
    if (blk < PREP_SPLIT) {
        size_t i = (size_t)blk * 256 + tid;
        float4 v = ((const float4*)X)[i];
        __nv_bfloat16 h0 = __float2bfloat16(v.x), h1 = __float2bfloat16(v.y);
        __nv_bfloat16 h2 = __float2bfloat16(v.z), h3 = __float2bfloat16(v.w);
        ((uint2*)g_Xhi)[i] = make_uint2(pack_bf(h0, h1), pack_bf(h2, h3));
        ((uint2*)g_Xlo)[i] = make_uint2(
            pack_bf(__float2bfloat16(v.x - __bfloat162float(h0)),
                    __float2bfloat16(v.y - __bfloat162float(h1))),
            pack_bf(__float2bfloat16(v.z - __bfloat162float(h2)),
                    __float2bfloat16(v.w - __bfloat162float(h3))));
        return;
    }
    if (tid < 128) {
        float ang = (float)tid / 64.0f;
        cs[tid] = cospif(ang);
        sn[tid] = sinpif(ang);
    }
    __syncthreads();
    blk -= PREP_SPLIT;
    if (blk < PREP_W1) {
        int idx = blk * 256 + tid;
        int d = idx / N1P_, c = idx - d * N1P_;
        float acc = 0.f;
        if (c < N1_) {
            int region = (c >= 1040) ? 1 : 0;
            int cc = c - region * 1040;
            int hd = cc / 130;
            int u = cc - hd * 130;
            int f = u >> 1;
            const float* w = w_qkv + (size_t)d * 3072 + region * 1024 + hd * 128;
            if ((u & 1) == 0) {
                #pragma unroll 8
                for (int dd = 0; dd < 128; dd++) acc += w[dd] * cs[(f * dd) & 127];
            } else {
                #pragma unroll 8
                for (int dd = 0; dd < 128; dd++) acc -= w[dd] * sn[(f * dd) & 127];
            }
            acc *= SCALE_;
        }
        __nv_bfloat16 hi = __float2bfloat16(acc);
        g_W1T_hi[c * 128 + d] = hi;
        g_W1T_lo[c * 128 + d] = __float2bfloat16(acc - __bfloat162float(hi));
        return;
    }
    blk -= PREP_W1;
    if (blk < PREP_W1V) {
        int idx = blk * 256 + tid;
        int d = idx / NK_, k = idx - d * NK_;
        int hd = k / 130;
        int u = k - hd * 130;
        int f = u >> 1;
        const float* w = w_qkv + (size_t)d * 3072 + 2048 + hd * 128;
        float acc = 0.f;
        if ((u & 1) == 0) {
            #pragma unroll 8
            for (int dd = 0; dd < 128; dd++) acc += w[dd] * cs[(f * dd) & 127];
        } else {
            #pragma unroll 8
            for (int dd = 0; dd < 128; dd++) acc -= w[dd] * sn[(f * dd) & 127];
        }
        g_W1v[idx] = acc;
        return;
    }
    blk -= PREP_W1V;
    {
        int idx = blk * 256 + tid;
        int o = idx & 127;
        int r = idx >> 7;
        int x = r % 65;
        int hp = r / 65;
        int p = hp & 1, hd = hp >> 1;
        float acc = 0.f;
        if (p == 0) {
            #pragma unroll 8
            for (int t2 = 0; t2 < 128; t2++)
                acc += cs[(x * t2) & 127] * w_out[(size_t)(hd * 128 + t2) * 128 + o];
            acc *= ((x == 0 || x == 64) ? 1.0f : 2.0f) / 128.0f;
        } else if (x != 0 && x != 64) {
            #pragma unroll 8
            for (int t2 = 0; t2 < 128; t2++)
                acc -= sn[(x * t2) & 127] * w_out[(size_t)(hd * 128 + t2) * 128 + o];
            acc *= 2.0f / 128.0f;
        }
        g_Mout[idx] = acc;
    }
}

// ---------------- GEMM1: |X@W1_qk| -> aq, ak [bh][f][e] (m256 x n128, 512 thr, 2-stage) ----------------
#define G1_STG 98304
__device__ __forceinline__ void g1_load(uint32_t sst, int bm, int bn, int k0, int tid) {
    #pragma unroll
    for (int u = tid; u < 2048; u += 512) {
        int r = u >> 3, cb = (u & 7) * 16;
        uint32_t d = swz64(r, cb);
        cp16(sst + d,         (const char*)g_Xhi + ((size_t)(bm + r) * 128 + k0) * 2 + cb);
        cp16(sst + 32768 + d, (const char*)g_Xlo + ((size_t)(bm + r) * 128 + k0) * 2 + cb);
    }
    #pragma unroll
    for (int u = tid; u < 1024; u += 512) {
        int r = u >> 3, cb = (u & 7) * 16;
        uint32_t d = swz64(r, cb);
        cp16(sst + 65536 + d, (const char*)g_W1T_hi + ((size_t)(bn + r) * 128 + k0) * 2 + cb);
        cp16(sst + 81920 + d, (const char*)g_W1T_lo + ((size_t)(bn + r) * 128 + k0) * 2 + cb);
    }
}

__global__ void __launch_bounds__(512, 1) gemm1_tc() {
    extern __shared__ char smem[];
    uint32_t sb = smem_u32(smem);
    int tid = threadIdx.x;
    int lane = tid & 31, wid = tid >> 5;
    int wm = wid & 7, wn = wid >> 3;      // 8 x 2 warps over 256 x 128
    int bm = blockIdx.y * 256, bn = blockIdx.x * 128;

    g1_load(sb, bm, bn, 0, tid);  cp_commit();
    g1_load(sb + G1_STG, bm, bn, 64, tid);  cp_commit();

    float c[2][8][4];
    #pragma unroll
    for (int i = 0; i < 2; i++)
        #pragma unroll
        for (int j = 0; j < 8; j++)
            #pragma unroll
            for (int k = 0; k < 4; k++) c[i][j][k] = 0.f;

    cp_wait1();
    __syncthreads();
    mma_chunk64(sb, sb + 32768, sb + 65536, sb + 81920, lane, wm, wn, c);
    cp_wait0();
    __syncthreads();
    mma_chunk64(sb + G1_STG, sb + G1_STG + 32768, sb + G1_STG + 65536,
                sb + G1_STG + 81920, lane, wm, wn, c);

    // epilogue: |q|,|k| into [bh][f][e] layout (coalesced 32B sectors per lane group)
    int g = lane >> 2, cp2 = (lane & 3) * 2;
    int bloc = (bm >> 11) * 8;               // b*8, constant per CTA
    #pragma unroll
    for (int tn = 0; tn < 8; tn++) {
        int col = bn + wn * 64 + tn * 8 + cp2;   // even
        if (col >= N1_) continue;
        int region = (col >= 1040) ? 1 : 0;
        int cc = col - region * 1040;
        int hd = cc / 130;
        int uu = cc - hd * 130;
        int f = uu >> 1;
        float* base = (region ? g_ak : g_aq) + ((size_t)(bloc + hd) * 65 + f) * 2048;
        #pragma unroll
        for (int tm = 0; tm < 2; tm++)
            #pragma unroll
            for (int hf = 0; hf < 2; hf++) {
                int e = (bm & 2047) + wm * 32 + tm * 16 + hf * 8 + g;
                float re = c[tm][tn][hf * 2], im = c[tm][tn][hf * 2 + 1];
                base[e] = sqrtf(re * re + im * im);
            }
    }
}

// ---------------- att partial: [f][e] layout, fully coalesced staging ----------------
__global__ void __launch_bounds__(256) att_partial_kernel() {
    __shared__ float aqs[65 * 68];
    __shared__ float aks[65 * 68];
    int bh = blockIdx.y;
    int chunk = blockIdx.x;
    int tid = threadIdx.x;
    int tx = tid & 15, ty = tid >> 4;
    int xs[5], ys[5];
    #pragma unroll
    for (int i = 0; i < 5; i++) {
        int x = tx + 16 * i; xs[i] = (x < 65) ? x : 0;
        int y = ty + 16 * i; ys[i] = (y < 65) ? y : 0;
    }
    float acc[5][5];
    #pragma unroll
    for (int i = 0; i < 5; i++)
        #pragma unroll
        for (int j = 0; j < 5; j++) acc[i][j] = 0.f;

    const float* aqsrc = g_aq + (size_t)bh * 65 * 2048;
    const float* aksrc = g_ak + (size_t)bh * 65 * 2048;
    int ebase = chunk * (2048 / EQ_);
    for (int e0 = ebase; e0 < ebase + 2048 / EQ_; e0 += 64) {
        for (int idx = tid; idx < 4160; idx += 256) {
            int f = idx >> 6, r = idx & 63;        // coalesced: e fastest
            size_t gidx = (size_t)f * 2048 + e0 + r;
            aqs[f * 68 + r] = aqsrc[gidx];
            aks[f * 68 + r] = aksrc[gidx];
        }
        __syncthreads();
        #pragma unroll 2
        for (int e4 = 0; e4 < 64; e4 += 4) {
            float4 av[5], bv[5];
            #pragma unroll
            for (int i = 0; i < 5; i++) av[i] = *(const float4*)&aqs[xs[i] * 68 + e4];
            #pragma unroll
            for (int j = 0; j < 5; j++) bv[j] = *(const float4*)&aks[ys[j] * 68 + e4];
            #pragma unroll
            for (int i = 0; i < 5; i++)
                #pragma unroll
                for (int j = 0; j < 5; j++) {
                    acc[i][j] += av[i].x * bv[j].x;
                    acc[i][j] += av[i].y * bv[j].y;
                    acc[i][j] += av[i].z * bv[j].z;
                    acc[i][j] += av[i].w * bv[j].w;
                }
        }
        __syncthreads();
    }
    float* dst = g_attp + (size_t)(bh * EQ_ + chunk) * 4225;
    #pragma unroll
    for (int i = 0; i < 5; i++) {
        int x = tx + 16 * i;
        if (x < 65)
            #pragma unroll
            for (int j = 0; j < 5; j++) {
                int y = ty + 16 * j;
                if (y < 65) dst[x * 65 + y] = acc[i][j];
            }
    }
}

// ---------------- softmax ----------------
__global__ void __launch_bounds__(256) att_softmax_kernel() {
    __shared__ float sm[4225];
    int bh = blockIdx.x;
    int tid = threadIdx.x;
    const float* p0 = g_attp + (size_t)(bh * EQ_) * 4225;
    for (int idx = tid; idx < 4225; idx += 256) {
        float s = 0.f;
        #pragma unroll
        for (int q = 0; q < EQ_; q++) s += p0[q * 4225 + idx];
        sm[idx] = s;
    }
    __syncthreads();
    int warp = tid >> 5, lane = tid & 31;
    for (int x = warp; x < 65; x += 8) {
        float m = -3.4e38f;
        for (int y = lane; y < 65; y += 32) m = fmaxf(m, sm[x * 65 + y]);
        #pragma unroll
        for (int o = 16; o; o >>= 1) m = fmaxf(m, __shfl_xor_sync(0xffffffffu, m, o));
        float s = 0.f;
        for (int y = lane; y < 65; y += 32) {
            float v = expf(sm[x * 65 + y] - m);
            sm[x * 65 + y] = v;
            s += v;
        }
        #pragma unroll
        for (int o = 16; o; o >>= 1) s += __shfl_xor_sync(0xffffffffu, s, o);
        float inv = 1.0f / s;
        for (int y = lane; y < 65; y += 32)
            g_att[(size_t)bh * 4225 + x * 65 + y] = sm[x * 65 + y] * inv;
    }
}

// ---------------- build C_b ----------------
__global__ void __launch_bounds__(256) build_c_kernel() {
    extern __shared__ float csm[];
    float* att_s = csm;
    float* mout_s = csm + 4225;
    int blk = blockIdx.x;                    // b*16 + h*2 + p
    int b = blk >> 4;
    int hp = blk & 15;
    int hd = hp >> 1, p = hp & 1;
    int tid = threadIdx.x;
    int bh = b * 8 + hd;
    for (int idx = tid; idx < 4225; idx += 256)
        att_s[idx] = g_att[(size_t)bh * 4225 + idx];
    for (int idx = tid; idx < 8320; idx += 256)
        mout_s[idx] = g_Mout[(size_t)hp * 8320 + idx];
    __syncthreads();
    for (int idx = tid; idx < 8320; idx += 256) {
        int o = idx / 65, y = idx - o * 65;
        float acc = 0.f;
        #pragma unroll 5
        for (int x = 0; x < 65; x++)
            acc += att_s[x * 65 + y] * mout_s[x * 128 + o];
        int k = hd * 130 + 2 * y + p;
        g_C[((size_t)b * NK_ + k) * 128 + o] = acc;
    }
}

// ---------------- build D_b = W1v @ C_b, split to DT hi/lo ----------------
__global__ void __launch_bounds__(256) build_d_kernel() {
    __shared__ float Wvs[128 * 65];
    __shared__ float Cs[65 * 32];
    int b = blockIdx.x;
    int o0 = blockIdx.y * 32;
    int tid = threadIdx.x;
    int ol = tid & 31, dg = tid >> 5;
    float acc[16];
    #pragma unroll
    for (int i = 0; i < 16; i++) acc[i] = 0.f;

    for (int k0 = 0; k0 < NK_; k0 += 65) {
        __syncthreads();
        for (int u = tid; u < 8320; u += 256) {
            int d = u / 65, kk = u - d * 65;
            Wvs[u] = g_W1v[(size_t)d * NK_ + k0 + kk];
        }
        for (int u = tid; u < 2080; u += 256) {
            int kk = u >> 5, oo = u & 31;
            Cs[u] = g_C[((size_t)b * NK_ + k0 + kk) * 128 + o0 + oo];
        }
        __syncthreads();
        #pragma unroll 5
        for (int kk = 0; kk < 65; kk++) {
            float cv = Cs[kk * 32 + ol];
            #pragma unroll
            for (int i = 0; i < 16; i++)
                acc[i] += Wvs[(dg + 8 * i) * 65 + kk] * cv;
        }
    }
    #pragma unroll
    for (int i = 0; i < 16; i++) {
        int d = dg + 8 * i;
        __nv_bfloat16 hi = __float2bfloat16(acc[i]);
        size_t off = ((size_t)b * 128 + o0 + ol) * 128 + d;
        g_DThi[off] = hi;
        g_DTlo[off] = __float2bfloat16(acc[i] - __bfloat162float(hi));
    }
}

// ---------------- final GEMM: out = X @ D_b + bias (m256, K=128, load-once) ----------------
#define FG_AHI 0
#define FG_ALO 65536
#define FG_BHI 131072
#define FG_BLO 163840
#define FG_TOT 196608
__global__ void __launch_bounds__(512, 1) final_gemm(float* __restrict__ out,
                                                     const float* __restrict__ bias) {
    extern __shared__ char smem[];
    uint32_t sb = smem_u32(smem);
    int tid = threadIdx.x;
    int lane = tid & 31, wid = tid >> 5;
    int wm = wid & 7, wn = wid >> 3;
    int bm = blockIdx.x * 256;
    int b = bm >> 11;

    #pragma unroll
    for (int u = tid; u < 4096; u += 512) {
        int r = u >> 4, seg = u & 15;
        int ch = seg >> 3, cb = (seg & 7) * 16;
        uint32_t d = ch * 32768 + swz64(r, cb);
        size_t src = (size_t)(bm + r) * 256 + ch * 128 + cb;
        cp16(sb + FG_AHI + d, (const char*)g_Xhi + src);
        cp16(sb + FG_ALO + d, (const char*)g_Xlo + src);
    }
    #pragma unroll
    for (int u = tid; u < 2048; u += 512) {
        int r = u >> 4, seg = u & 15;
        int ch = seg >> 3, cb = (seg & 7) * 16;
        uint32_t d = ch * 16384 + swz64(r, cb);
        size_t src = ((size_t)(b * 128 + r)) * 256 + ch * 128 + cb;
        cp16(sb + FG_BHI + d, (const char*)g_DThi + src);
        cp16(sb + FG_BLO + d, (const char*)g_DTlo + src);
    }
    cp_commit();
    cp_wait0();
    __syncthreads();

    float c[2][8][4];
    #pragma unroll
    for (int i = 0; i < 2; i++)
        #pragma unroll
        for (int j = 0; j < 8; j++)
            #pragma unroll
            for (int k = 0; k < 4; k++) c[i][j][k] = 0.f;

    #pragma unroll
    for (int ch = 0; ch < 2; ch++)
        mma_chunk64(sb + FG_AHI + ch * 32768, sb + FG_ALO + ch * 32768,
                    sb + FG_BHI + ch * 16384, sb + FG_BLO + ch * 16384,
                    lane, wm, wn, c);

    int g = lane >> 2, cp2 = (lane & 3) * 2;
    #pragma unroll
    for (int tm = 0; tm < 2; tm++)
        #pragma unroll
        for (int hf = 0; hf < 2; hf++) {
            size_t row = (size_t)bm + wm * 32 + tm * 16 + hf * 8 + g;
            float* dst = out + row * 128;
            #pragma unroll
            for (int tn = 0; tn < 8; tn++) {
                int col = wn * 64 + tn * 8 + cp2;
                float2 bv = *(const float2*)(bias + col);
                *(float2*)(dst + col) = make_float2(c[tm][tn][hf * 2] + bv.x,
                                                    c[tm][tn][hf * 2 + 1] + bv.y);
            }
        }
}

// ---------------- launch ----------------
extern "C" void kernel_launch(void* const* d_in, const int* in_sizes, int n_in,
                              void* d_out, int out_size) {
    const float* x     = (const float*)d_in[0];
    const float* w_qkv = (const float*)d_in[1];
    const float* w_out = (const float*)d_in[2];
    const float* b_out = (const float*)d_in[3];
    float* out = (float*)d_out;

    cudaFuncSetAttribute(gemm1_tc, cudaFuncAttributeMaxDynamicSharedMemorySize, 2 * G1_STG);
    cudaFuncSetAttribute(final_gemm, cudaFuncAttributeMaxDynamicSharedMemorySize, FG_TOT);
    cudaFuncSetAttribute(build_c_kernel, cudaFuncAttributeMaxDynamicSharedMemorySize,
                         (4225 + 8320) * 4);

    prep_kernel<<<PREP_TOTAL, 256>>>(x, w_qkv, w_out);
    gemm1_tc<<<dim3(N1P_ / 128, ROWS_ / 256), 512, 2 * G1_STG>>>();
    att_partial_kernel<<<dim3(EQ_, B_ * H_), 256>>>();
    att_softmax_kernel<<<B_ * H_, 256>>>();
    build_c_kernel<<<B_ * H_ * 2, 256, (4225 + 8320) * 4>>>();
    build_d_kernel<<<dim3(B_, 4), 256>>>();
    final_gemm<<<ROWS_ / 256, 512, FG_TOT>>>(out, b_out);
}

// round 12
// speedup vs baseline: 1.5715x; 1.0502x over previous
#include <cuda_runtime.h>
#include <cuda_bf16.h>
#include <cstdint>
#include <math.h>

// Problem constants
#define B_    16
#define N_    2048
#define D_    128
#define H_    8
#define F_    65
#define ROWS_ 32768
#define N1_   2080       // q,k: 2 regions * 8 heads * 130 (re/im interleaved u=2f+p)
#define N1P_  2176       // 17 n-tiles of 128
#define NK_   1040
#define SCALE_ (1.0f/65.0f)
#define EQ_   8

// ---------------- scratch (static device, no allocation) ----------------
__device__ __nv_bfloat16 g_Xhi[(size_t)ROWS_ * D_];
__device__ __nv_bfloat16 g_Xlo[(size_t)ROWS_ * D_];
__device__ __nv_bfloat16 g_W1T_hi[N1P_ * D_];
__device__ __nv_bfloat16 g_W1T_lo[N1P_ * D_];
__device__ float g_W1v[D_ * NK_];
__device__ float g_Mout[H_ * 2 * F_ * D_];       // [h][p][x][o]
__device__ float g_aq[(size_t)B_ * H_ * F_ * N_]; // [bh][f][e]
__device__ float g_ak[(size_t)B_ * H_ * F_ * N_];
__device__ float g_attp[B_ * H_ * EQ_ * F_ * F_];
__device__ float g_att[B_ * H_ * F_ * F_];
__device__ float g_C[B_ * NK_ * D_];             // [b][k][o]
__device__ __nv_bfloat16 g_DThi[B_ * D_ * D_];
__device__ __nv_bfloat16 g_DTlo[B_ * D_ * D_];

// ---------------- helpers ----------------
__device__ __forceinline__ uint32_t smem_u32(const void* p) {
    uint32_t a;
    asm("{ .reg .u64 t; cvta.to.shared.u64 t, %1; cvt.u32.u64 %0, t; }" : "=r"(a) : "l"(p));
    return a;
}
__device__ __forceinline__ void ldsm_x4(uint32_t* r, uint32_t addr) {
    asm volatile("ldmatrix.sync.aligned.m8n8.x4.shared.b16 {%0,%1,%2,%3}, [%4];"
                 : "=r"(r[0]), "=r"(r[1]), "=r"(r[2]), "=r"(r[3]) : "r"(addr));
}
__device__ __forceinline__ void mma16816(float* c, const uint32_t* a, const uint32_t* b) {
    asm volatile("mma.sync.aligned.m16n8k16.row.col.f32.bf16.bf16.f32 "
                 "{%0,%1,%2,%3}, {%4,%5,%6,%7}, {%8,%9}, {%0,%1,%2,%3};"
                 : "+f"(c[0]), "+f"(c[1]), "+f"(c[2]), "+f"(c[3])
                 : "r"(a[0]), "r"(a[1]), "r"(a[2]), "r"(a[3]), "r"(b[0]), "r"(b[1]));
}
#define FMA_F32X2(d, a, b) \
    asm("fma.rn.f32x2 %0, %1, %2, %0;" : "+l"(d) : "l"(a), "l"(b))
__device__ __forceinline__ uint32_t pack_bf(__nv_bfloat16 a, __nv_bfloat16 b) {
    __nv_bfloat162 p = __halves2bfloat162(a, b);
    return *reinterpret_cast<uint32_t*>(&p);
}
// swizzled offset within a [rows][64 bf16] tile (row = 128 bytes)
__device__ __forceinline__ uint32_t swz64(int row, int colbyte) {
    return (uint32_t)(row * 128 + (colbyte ^ ((row & 7) << 4)));
}
__device__ __forceinline__ void cp16(uint32_t dst, const void* src) {
    asm volatile("cp.async.cg.shared.global [%0], [%1], 16;" :: "r"(dst), "l"(src));
}
__device__ __forceinline__ void cp_commit() { asm volatile("cp.async.commit_group;"); }
__device__ __forceinline__ void cp_wait0() { asm volatile("cp.async.wait_group 0;" ::: "memory"); }
__device__ __forceinline__ void cp_wait1() { asm volatile("cp.async.wait_group 1;" ::: "memory"); }

// fused 3-product sweep over one resident [*x64] K-chunk (4 k-steps).
// Per k-step: 12 ldsm feed 48 mma.
__device__ __forceinline__ void mma_chunk64(uint32_t sAhi, uint32_t sAlo,
                                            uint32_t sBhi, uint32_t sBlo,
                                            int lane, int wm, int wn, float c[2][8][4]) {
    #pragma unroll
    for (int ks = 0; ks < 4; ks++) {
        int colb = ks * 32 + (lane >> 4) * 16;
        int ar = wm * 32 + (lane & 15);
        uint32_t ahi[2][4], alo[2][4];
        #pragma unroll
        for (int tm = 0; tm < 2; tm++)
            ldsm_x4(ahi[tm], sAhi + swz64(ar + tm * 16, colb));
        uint32_t bhi[8][2], blo[8][2];
        #pragma unroll
        for (int ng = 0; ng < 4; ng++) {
            int n = wn * 64 + ng * 16 + (lane & 15);
            uint32_t q[4];
            ldsm_x4(q, sBhi + swz64(n, colb));
            bhi[2 * ng][0] = q[0]; bhi[2 * ng + 1][0] = q[1];
            bhi[2 * ng][1] = q[2]; bhi[2 * ng + 1][1] = q[3];
        }
        #pragma unroll
        for (int tm = 0; tm < 2; tm++)
            #pragma unroll
            for (int tn = 0; tn < 8; tn++)
                mma16816(c[tm][tn], ahi[tm], bhi[tn]);
        #pragma unroll
        for (int ng = 0; ng < 4; ng++) {
            int n = wn * 64 + ng * 16 + (lane & 15);
            uint32_t q[4];
            ldsm_x4(q, sBlo + swz64(n, colb));
            blo[2 * ng][0] = q[0]; blo[2 * ng + 1][0] = q[1];
            blo[2 * ng][1] = q[2]; blo[2 * ng + 1][1] = q[3];
        }
        #pragma unroll
        for (int tm = 0; tm < 2; tm++)
            #pragma unroll
            for (int tn = 0; tn < 8; tn++)
                mma16816(c[tm][tn], ahi[tm], blo[tn]);
        #pragma unroll
        for (int tm = 0; tm < 2; tm++)
            ldsm_x4(alo[tm], sAlo + swz64(ar + tm * 16, colb));
        #pragma unroll
        for (int tm = 0; tm < 2; tm++)
            #pragma unroll
            for (int tn = 0; tn < 8; tn++)
                mma16816(c[tm][tn], alo[tm], bhi[tn]);
    }
}

// ---------------- merged prep ----------------
#define PREP_SPLIT  4096
#define PREP_W1     1088
#define PREP_W1V    520
#define PREP_MOUT   520
#define PREP_TOTAL  (PREP_SPLIT + PREP_W1 + PREP_W1V + PREP_MOUT)

__global__ void __launch_bounds__(256) prep_kernel(const float* __restrict__ X,
                                                   const float* __restrict__ w_qkv,
                                                   const float* __restrict__ w_out) {
    __shared__ float cs[128], sn[128];
    int tid = threadIdx.x;
    int blk = blockIdx.x;
    if (blk < PREP_SPLIT) {
        size_t i = (size_t)blk * 256 + tid;
        float4 v = ((const float4*)X)[i];
        __nv_bfloat16 h0 = __float2bfloat16(v.x), h1 = __float2bfloat16(v.y);
        __nv_bfloat16 h2 = __float2bfloat16(v.z), h3 = __float2bfloat16(v.w);
        ((uint2*)g_Xhi)[i] = make_uint2(pack_bf(h0, h1), pack_bf(h2, h3));
        ((uint2*)g_Xlo)[i] = make_uint2(
            pack_bf(__float2bfloat16(v.x - __bfloat162float(h0)),
                    __float2bfloat16(v.y - __bfloat162float(h1))),
            pack_bf(__float2bfloat16(v.z - __bfloat162float(h2)),
                    __float2bfloat16(v.w - __bfloat162float(h3))));
        return;
    }
    if (tid < 128) {
        float ang = (float)tid / 64.0f;
        cs[tid] = cospif(ang);
        sn[tid] = sinpif(ang);
    }
    __syncthreads();
    blk -= PREP_SPLIT;
    if (blk < PREP_W1) {
        int idx = blk * 256 + tid;
        int d = idx / N1P_, c = idx - d * N1P_;
        float acc = 0.f;
        if (c < N1_) {
            int region = (c >= 1040) ? 1 : 0;
            int cc = c - region * 1040;
            int hd = cc / 130;
            int u = cc - hd * 130;
            int f = u >> 1;
            const float* w = w_qkv + (size_t)d * 3072 + region * 1024 + hd * 128;
            if ((u & 1) == 0) {
                #pragma unroll 8
                for (int dd = 0; dd < 128; dd++) acc += w[dd] * cs[(f * dd) & 127];
            } else {
                #pragma unroll 8
                for (int dd = 0; dd < 128; dd++) acc -= w[dd] * sn[(f * dd) & 127];
            }
            acc *= SCALE_;
        }
        __nv_bfloat16 hi = __float2bfloat16(acc);
        g_W1T_hi[c * 128 + d] = hi;
        g_W1T_lo[c * 128 + d] = __float2bfloat16(acc - __bfloat162float(hi));
        return;
    }
    blk -= PREP_W1;
    if (blk < PREP_W1V) {
        int idx = blk * 256 + tid;
        int d = idx / NK_, k = idx - d * NK_;
        int hd = k / 130;
        int u = k - hd * 130;
        int f = u >> 1;
        const float* w = w_qkv + (size_t)d * 3072 + 2048 + hd * 128;
        float acc = 0.f;
        if ((u & 1) == 0) {
            #pragma unroll 8
            for (int dd = 0; dd < 128; dd++) acc += w[dd] * cs[(f * dd) & 127];
        } else {
            #pragma unroll 8
            for (int dd = 0; dd < 128; dd++) acc -= w[dd] * sn[(f * dd) & 127];
        }
        g_W1v[idx] = acc;
        return;
    }
    blk -= PREP_W1V;
    {
        int idx = blk * 256 + tid;
        int o = idx & 127;
        int r = idx >> 7;
        int x = r % 65;
        int hp = r / 65;
        int p = hp & 1, hd = hp >> 1;
        float acc = 0.f;
        if (p == 0) {
            #pragma unroll 8
            for (int t2 = 0; t2 < 128; t2++)
                acc += cs[(x * t2) & 127] * w_out[(size_t)(hd * 128 + t2) * 128 + o];
            acc *= ((x == 0 || x == 64) ? 1.0f : 2.0f) / 128.0f;
        } else if (x != 0 && x != 64) {
            #pragma unroll 8
            for (int t2 = 0; t2 < 128; t2++)
                acc -= sn[(x * t2) & 127] * w_out[(size_t)(hd * 128 + t2) * 128 + o];
            acc *= 2.0f / 128.0f;
        }
        g_Mout[idx] = acc;
    }
}

// ---------------- GEMM1: |X@W1_qk| -> aq, ak [bh][f][e] (m256 x n128, 512 thr, 2-stage) ----------------
#define G1_STG 98304
__device__ __forceinline__ void g1_load(uint32_t sst, int bm, int bn, int k0, int tid) {
    #pragma unroll
    for (int u = tid; u < 2048; u += 512) {
        int r = u >> 3, cb = (u & 7) * 16;
        uint32_t d = swz64(r, cb);
        cp16(sst + d,         (const char*)g_Xhi + ((size_t)(bm + r) * 128 + k0) * 2 + cb);
        cp16(sst + 32768 + d, (const char*)g_Xlo + ((size_t)(bm + r) * 128 + k0) * 2 + cb);
    }
    #pragma unroll
    for (int u = tid; u < 1024; u += 512) {
        int r = u >> 3, cb = (u & 7) * 16;
        uint32_t d = swz64(r, cb);
        cp16(sst + 65536 + d, (const char*)g_W1T_hi + ((size_t)(bn + r) * 128 + k0) * 2 + cb);
        cp16(sst + 81920 + d, (const char*)g_W1T_lo + ((size_t)(bn + r) * 128 + k0) * 2 + cb);
    }
}

__global__ void __launch_bounds__(512, 1) gemm1_tc() {
    extern __shared__ char smem[];
    uint32_t sb = smem_u32(smem);
    int tid = threadIdx.x;
    int lane = tid & 31, wid = tid >> 5;
    int wm = wid & 7, wn = wid >> 3;      // 8 x 2 warps over 256 x 128
    int bm = blockIdx.y * 256, bn = blockIdx.x * 128;

    g1_load(sb, bm, bn, 0, tid);  cp_commit();
    g1_load(sb + G1_STG, bm, bn, 64, tid);  cp_commit();

    float c[2][8][4];
    #pragma unroll
    for (int i = 0; i < 2; i++)
        #pragma unroll
        for (int j = 0; j < 8; j++)
            #pragma unroll
            for (int k = 0; k < 4; k++) c[i][j][k] = 0.f;

    cp_wait1();
    __syncthreads();
    mma_chunk64(sb, sb + 32768, sb + 65536, sb + 81920, lane, wm, wn, c);
    cp_wait0();
    __syncthreads();
    mma_chunk64(sb + G1_STG, sb + G1_STG + 32768, sb + G1_STG + 65536,
                sb + G1_STG + 81920, lane, wm, wn, c);

    // epilogue: |q|,|k| into [bh][f][e] layout
    int g = lane >> 2, cp2 = (lane & 3) * 2;
    int bloc = (bm >> 11) * 8;               // b*8, constant per CTA
    #pragma unroll
    for (int tn = 0; tn < 8; tn++) {
        int col = bn + wn * 64 + tn * 8 + cp2;   // even
        if (col >= N1_) continue;
        int region = (col >= 1040) ? 1 : 0;
        int cc = col - region * 1040;
        int hd = cc / 130;
        int uu = cc - hd * 130;
        int f = uu >> 1;
        float* base = (region ? g_ak : g_aq) + ((size_t)(bloc + hd) * 65 + f) * 2048;
        #pragma unroll
        for (int tm = 0; tm < 2; tm++)
            #pragma unroll
            for (int hf = 0; hf < 2; hf++) {
                int e = (bm & 2047) + wm * 32 + tm * 16 + hf * 8 + g;
                float re = c[tm][tn][hf * 2], im = c[tm][tn][hf * 2 + 1];
                base[e] = sqrtf(re * re + im * im);
            }
    }
}

// ---------------- att partial: [f][e] layout, packed f32x2 FMA ----------------
__global__ void __launch_bounds__(256) att_partial_kernel() {
    __shared__ float aqs[65 * 66];
    __shared__ float aks[65 * 66];
    int bh = blockIdx.y;
    int chunk = blockIdx.x;
    int tid = threadIdx.x;
    int tx = tid & 15, ty = tid >> 4;
    int xs[5], ys[5];
    #pragma unroll
    for (int i = 0; i < 5; i++) {
        int x = tx + 16 * i; xs[i] = (x < 65) ? x : 0;
        int y = ty + 16 * i; ys[i] = (y < 65) ? y : 0;
    }
    unsigned long long acc2[5][5];
    #pragma unroll
    for (int i = 0; i < 5; i++)
        #pragma unroll
        for (int j = 0; j < 5; j++) acc2[i][j] = 0ull;   // packed (0.f, 0.f)

    const float* aqsrc = g_aq + (size_t)bh * 65 * 2048;
    const float* aksrc = g_ak + (size_t)bh * 65 * 2048;
    int ebase = chunk * (2048 / EQ_);
    for (int e0 = ebase; e0 < ebase + 2048 / EQ_; e0 += 64) {
        for (int idx = tid; idx < 4160; idx += 256) {
            int f = idx >> 6, r = idx & 63;        // coalesced: e fastest
            size_t gidx = (size_t)f * 2048 + e0 + r;
            aqs[f * 66 + r] = aqsrc[gidx];
            aks[f * 66 + r] = aksrc[gidx];
        }
        __syncthreads();
        #pragma unroll 4
        for (int e2 = 0; e2 < 64; e2 += 2) {
            unsigned long long av[5], bv[5];
            #pragma unroll
            for (int i = 0; i < 5; i++)
                av[i] = *(const unsigned long long*)&aqs[xs[i] * 66 + e2];
            #pragma unroll
            for (int j = 0; j < 5; j++)
                bv[j] = *(const unsigned long long*)&aks[ys[j] * 66 + e2];
            #pragma unroll
            for (int i = 0; i < 5; i++)
                #pragma unroll
                for (int j = 0; j < 5; j++)
                    FMA_F32X2(acc2[i][j], av[i], bv[j]);
        }
        __syncthreads();
    }
    float* dst = g_attp + (size_t)(bh * EQ_ + chunk) * 4225;
    #pragma unroll
    for (int i = 0; i < 5; i++) {
        int x = tx + 16 * i;
        if (x < 65)
            #pragma unroll
            for (int j = 0; j < 5; j++) {
                int y = ty + 16 * j;
                if (y < 65) {
                    float lo = __uint_as_float((uint32_t)(acc2[i][j] & 0xffffffffull));
                    float hi = __uint_as_float((uint32_t)(acc2[i][j] >> 32));
                    dst[x * 65 + y] = lo + hi;
                }
            }
    }
}

// ---------------- softmax: one warp per x-row, 9x wider grid ----------------
__global__ void __launch_bounds__(256) att_softmax_kernel() {
    int bh = blockIdx.y;
    int warp = threadIdx.x >> 5, lane = threadIdx.x & 31;
    int x = blockIdx.x * 8 + warp;
    if (x >= 65) return;
    const float* p0 = g_attp + (size_t)(bh * EQ_) * 4225 + x * 65;
    float v[3];     // y = lane, lane+32, lane+64 (y<65)
    float m = -3.4e38f;
    #pragma unroll
    for (int t = 0; t < 3; t++) {
        int y = lane + t * 32;
        float s = 0.f;
        if (y < 65) {
            #pragma unroll
            for (int q = 0; q < EQ_; q++) s += p0[q * 4225 + y];
        } else s = -3.4e38f;
        v[t] = s;
        m = fmaxf(m, s);
    }
    #pragma unroll
    for (int o = 16; o; o >>= 1) m = fmaxf(m, __shfl_xor_sync(0xffffffffu, m, o));
    float sum = 0.f;
    #pragma unroll
    for (int t = 0; t < 3; t++) {
        int y = lane + t * 32;
        if (y < 65) {
            v[t] = expf(v[t] - m);
            sum += v[t];
        }
    }
    #pragma unroll
    for (int o = 16; o; o >>= 1) sum += __shfl_xor_sync(0xffffffffu, sum, o);
    float inv = 1.0f / sum;
    float* dst = g_att + (size_t)bh * 4225 + x * 65;
    #pragma unroll
    for (int t = 0; t < 3; t++) {
        int y = lane + t * 32;
        if (y < 65) dst[y] = v[t] * inv;
    }
}

// ---------------- build C_b ----------------
__global__ void __launch_bounds__(256) build_c_kernel() {
    extern __shared__ float csm[];
    float* att_s = csm;
    float* mout_s = csm + 4225;
    int blk = blockIdx.x;                    // b*16 + h*2 + p
    int b = blk >> 4;
    int hp = blk & 15;
    int hd = hp >> 1, p = hp & 1;
    int tid = threadIdx.x;
    int bh = b * 8 + hd;
    for (int idx = tid; idx < 4225; idx += 256)
        att_s[idx] = g_att[(size_t)bh * 4225 + idx];
    for (int idx = tid; idx < 8320; idx += 256)
        mout_s[idx] = g_Mout[(size_t)hp * 8320 + idx];
    __syncthreads();
    for (int idx = tid; idx < 8320; idx += 256) {
        int o = idx / 65, y = idx - o * 65;
        float acc = 0.f;
        #pragma unroll 5
        for (int x = 0; x < 65; x++)
            acc += att_s[x * 65 + y] * mout_s[x * 128 + o];
        int k = hd * 130 + 2 * y + p;
        g_C[((size_t)b * NK_ + k) * 128 + o] = acc;
    }
}

// ---------------- build D_b = W1v @ C_b, split to DT hi/lo ----------------
__global__ void __launch_bounds__(256) build_d_kernel() {
    __shared__ float Wvs[128 * 65];
    __shared__ float Cs[65 * 32];
    int b = blockIdx.x;
    int o0 = blockIdx.y * 32;
    int tid = threadIdx.x;
    int ol = tid & 31, dg = tid >> 5;
    float acc[16];
    #pragma unroll
    for (int i = 0; i < 16; i++) acc[i] = 0.f;

    for (int k0 = 0; k0 < NK_; k0 += 65) {
        __syncthreads();
        for (int u = tid; u < 8320; u += 256) {
            int d = u / 65, kk = u - d * 65;
            Wvs[u] = g_W1v[(size_t)d * NK_ + k0 + kk];
        }
        for (int u = tid; u < 2080; u += 256) {
            int kk = u >> 5, oo = u & 31;
            Cs[u] = g_C[((size_t)b * NK_ + k0 + kk) * 128 + o0 + oo];
        }
        __syncthreads();
        #pragma unroll 5
        for (int kk = 0; kk < 65; kk++) {
            float cv = Cs[kk * 32 + ol];
            #pragma unroll
            for (int i = 0; i < 16; i++)
                acc[i] += Wvs[(dg + 8 * i) * 65 + kk] * cv;
        }
    }
    #pragma unroll
    for (int i = 0; i < 16; i++) {
        int d = dg + 8 * i;
        __nv_bfloat16 hi = __float2bfloat16(acc[i]);
        size_t off = ((size_t)b * 128 + o0 + ol) * 128 + d;
        g_DThi[off] = hi;
        g_DTlo[off] = __float2bfloat16(acc[i] - __bfloat162float(hi));
    }
}

// ---------------- final GEMM: out = X @ D_b + bias (m256, K=128, 2-group pipelined load) ----------------
#define FG_AHI 0
#define FG_ALO 65536
#define FG_BHI 131072
#define FG_BLO 163840
#define FG_TOT 196608
__global__ void __launch_bounds__(512, 1) final_gemm(float* __restrict__ out,
                                                     const float* __restrict__ bias) {
    extern __shared__ char smem[];
    uint32_t sb = smem_u32(smem);
    int tid = threadIdx.x;
    int lane = tid & 31, wid = tid >> 5;
    int wm = wid & 7, wn = wid >> 3;
    int bm = blockIdx.x * 256;
    int b = bm >> 11;

    // two commit groups: K-chunk 0 then K-chunk 1, so mma on ch0 overlaps ch1 load
    #pragma unroll
    for (int ch = 0; ch < 2; ch++) {
        #pragma unroll
        for (int u = tid; u < 2048; u += 512) {
            int r = u >> 3, cb = (u & 7) * 16;
            uint32_t d = ch * 32768 + swz64(r, cb);
            size_t src = (size_t)(bm + r) * 256 + ch * 128 + cb;
            cp16(sb + FG_AHI + d, (const char*)g_Xhi + src);
            cp16(sb + FG_ALO + d, (const char*)g_Xlo + src);
        }
        #pragma unroll
        for (int u = tid; u < 1024; u += 512) {
            int r = u >> 3, cb = (u & 7) * 16;
            uint32_t d = ch * 16384 + swz64(r, cb);
            size_t src = ((size_t)(b * 128 + r)) * 256 + ch * 128 + cb;
            cp16(sb + FG_BHI + d, (const char*)g_DThi + src);
            cp16(sb + FG_BLO + d, (const char*)g_DTlo + src);
        }
        cp_commit();
    }

    float c[2][8][4];
    #pragma unroll
    for (int i = 0; i < 2; i++)
        #pragma unroll
        for (int j = 0; j < 8; j++)
            #pragma unroll
            for (int k = 0; k < 4; k++) c[i][j][k] = 0.f;

    cp_wait1();
    __syncthreads();
    mma_chunk64(sb + FG_AHI, sb + FG_ALO, sb + FG_BHI, sb + FG_BLO, lane, wm, wn, c);
    cp_wait0();
    __syncthreads();
    mma_chunk64(sb + FG_AHI + 32768, sb + FG_ALO + 32768,
                sb + FG_BHI + 16384, sb + FG_BLO + 16384, lane, wm, wn, c);

    int g = lane >> 2, cp2 = (lane & 3) * 2;
    #pragma unroll
    for (int tm = 0; tm < 2; tm++)
        #pragma unroll
        for (int hf = 0; hf < 2; hf++) {
            size_t row = (size_t)bm + wm * 32 + tm * 16 + hf * 8 + g;
            float* dst = out + row * 128;
            #pragma unroll
            for (int tn = 0; tn < 8; tn++) {
                int col = wn * 64 + tn * 8 + cp2;
                float2 bv = *(const float2*)(bias + col);
                *(float2*)(dst + col) = make_float2(c[tm][tn][hf * 2] + bv.x,
                                                    c[tm][tn][hf * 2 + 1] + bv.y);
            }
        }
}

// ---------------- launch ----------------
extern "C" void kernel_launch(void* const* d_in, const int* in_sizes, int n_in,
                              void* d_out, int out_size) {
    const float* x     = (const float*)d_in[0];
    const float* w_qkv = (const float*)d_in[1];
    const float* w_out = (const float*)d_in[2];
    const float* b_out = (const float*)d_in[3];
    float* out = (float*)d_out;

    cudaFuncSetAttribute(gemm1_tc, cudaFuncAttributeMaxDynamicSharedMemorySize, 2 * G1_STG);
    cudaFuncSetAttribute(final_gemm, cudaFuncAttributeMaxDynamicSharedMemorySize, FG_TOT);
    cudaFuncSetAttribute(build_c_kernel, cudaFuncAttributeMaxDynamicSharedMemorySize,
                         (4225 + 8320) * 4);

    prep_kernel<<<PREP_TOTAL, 256>>>(x, w_qkv, w_out);
    gemm1_tc<<<dim3(N1P_ / 128, ROWS_ / 256), 512, 2 * G1_STG>>>();
    att_partial_kernel<<<dim3(EQ_, B_ * H_), 256>>>();
    att_softmax_kernel<<<dim3(9, B_ * H_), 256>>>();
    build_c_kernel<<<B_ * H_ * 2, 256, (4225 + 8320) * 4>>>();
    build_d_kernel<<<dim3(B_, 4), 256>>>();
    final_gemm<<<ROWS_ / 256, 512, FG_TOT>>>(out, b_out);
}

// round 13
// speedup vs baseline: 1.6998x; 1.0817x over previous
#include <cuda_runtime.h>
#include <cuda_bf16.h>
#include <cuda_fp16.h>
#include <cstdint>
#include <math.h>

// Problem constants
#define B_    16
#define N_    2048
#define D_    128
#define H_    8
#define F_    65
#define ROWS_ 32768
#define N1_   2080       // q,k: 2 regions * 8 heads * 130 (re/im interleaved u=2f+p)
#define N1P_  2176       // 17 n-tiles of 128
#define NK_   1040
#define SCALE_ (1.0f/65.0f)
#define EQ_   8

// ---------------- scratch (static device, no allocation) ----------------
__device__ __nv_bfloat16 g_Xhi[(size_t)ROWS_ * D_];   // bf16 split for final_gemm
__device__ __nv_bfloat16 g_Xlo[(size_t)ROWS_ * D_];
__device__ __half g_X16[(size_t)ROWS_ * D_];          // single fp16 X for gemm1
__device__ __half g_W1T_h16[N1P_ * D_];               // fp16 hi/lo folded q,k weights
__device__ __half g_W1T_l16[N1P_ * D_];
__device__ float g_W1v[D_ * NK_];
__device__ float g_Mout[H_ * 2 * F_ * D_];            // [h][p][x][o]
__device__ float g_aq[(size_t)B_ * H_ * F_ * N_];     // [bh][f][e]
__device__ float g_ak[(size_t)B_ * H_ * F_ * N_];
__device__ float g_attp[B_ * H_ * EQ_ * F_ * F_];
__device__ float g_att[B_ * H_ * F_ * F_];
__device__ float g_C[B_ * NK_ * D_];                  // [b][k][o]
__device__ __nv_bfloat16 g_DThi[B_ * D_ * D_];
__device__ __nv_bfloat16 g_DTlo[B_ * D_ * D_];

// ---------------- helpers ----------------
__device__ __forceinline__ uint32_t smem_u32(const void* p) {
    uint32_t a;
    asm("{ .reg .u64 t; cvta.to.shared.u64 t, %1; cvt.u32.u64 %0, t; }" : "=r"(a) : "l"(p));
    return a;
}
__device__ __forceinline__ void ldsm_x4(uint32_t* r, uint32_t addr) {
    asm volatile("ldmatrix.sync.aligned.m8n8.x4.shared.b16 {%0,%1,%2,%3}, [%4];"
                 : "=r"(r[0]), "=r"(r[1]), "=r"(r[2]), "=r"(r[3]) : "r"(addr));
}
__device__ __forceinline__ void mma16816_bf(float* c, const uint32_t* a, const uint32_t* b) {
    asm volatile("mma.sync.aligned.m16n8k16.row.col.f32.bf16.bf16.f32 "
                 "{%0,%1,%2,%3}, {%4,%5,%6,%7}, {%8,%9}, {%0,%1,%2,%3};"
                 : "+f"(c[0]), "+f"(c[1]), "+f"(c[2]), "+f"(c[3])
                 : "r"(a[0]), "r"(a[1]), "r"(a[2]), "r"(a[3]), "r"(b[0]), "r"(b[1]));
}
__device__ __forceinline__ void mma16816_f16(float* c, const uint32_t* a, const uint32_t* b) {
    asm volatile("mma.sync.aligned.m16n8k16.row.col.f32.f16.f16.f32 "
                 "{%0,%1,%2,%3}, {%4,%5,%6,%7}, {%8,%9}, {%0,%1,%2,%3};"
                 : "+f"(c[0]), "+f"(c[1]), "+f"(c[2]), "+f"(c[3])
                 : "r"(a[0]), "r"(a[1]), "r"(a[2]), "r"(a[3]), "r"(b[0]), "r"(b[1]));
}
#define FMA_F32X2(d, a, b) \
    asm("fma.rn.f32x2 %0, %1, %2, %0;" : "+l"(d) : "l"(a), "l"(b))
__device__ __forceinline__ uint32_t pack_bf(__nv_bfloat16 a, __nv_bfloat16 b) {
    __nv_bfloat162 p = __halves2bfloat162(a, b);
    return *reinterpret_cast<uint32_t*>(&p);
}
// swizzled offset within a [rows][64 x 16bit] tile (row = 128 bytes)
__device__ __forceinline__ uint32_t swz64(int row, int colbyte) {
    return (uint32_t)(row * 128 + (colbyte ^ ((row & 7) << 4)));
}
__device__ __forceinline__ void cp16(uint32_t dst, const void* src) {
    asm volatile("cp.async.cg.shared.global [%0], [%1], 16;" :: "r"(dst), "l"(src));
}
__device__ __forceinline__ void cp_commit() { asm volatile("cp.async.commit_group;"); }
__device__ __forceinline__ void cp_wait0() { asm volatile("cp.async.wait_group 0;" ::: "memory"); }
__device__ __forceinline__ void cp_wait1() { asm volatile("cp.async.wait_group 1;" ::: "memory"); }

// ---------------- merged prep ----------------
#define PREP_SPLIT  4096
#define PREP_W1     1088
#define PREP_W1V    520
#define PREP_MOUT   520
#define PREP_TOTAL  (PREP_SPLIT + PREP_W1 + PREP_W1V + PREP_MOUT)

__global__ void __launch_bounds__(256) prep_kernel(const float* __restrict__ X,
                                                   const float* __restrict__ w_qkv,
                                                   const float* __restrict__ w_out) {
    __shared__ float cs[128], sn[128];
    int tid = threadIdx.x;
    int blk = blockIdx.x;
    if (blk < PREP_SPLIT) {
        size_t i = (size_t)blk * 256 + tid;
        float4 v = ((const float4*)X)[i];
        __nv_bfloat16 h0 = __float2bfloat16(v.x), h1 = __float2bfloat16(v.y);
        __nv_bfloat16 h2 = __float2bfloat16(v.z), h3 = __float2bfloat16(v.w);
        ((uint2*)g_Xhi)[i] = make_uint2(pack_bf(h0, h1), pack_bf(h2, h3));
        ((uint2*)g_Xlo)[i] = make_uint2(
            pack_bf(__float2bfloat16(v.x - __bfloat162float(h0)),
                    __float2bfloat16(v.y - __bfloat162float(h1))),
            pack_bf(__float2bfloat16(v.z - __bfloat162float(h2)),
                    __float2bfloat16(v.w - __bfloat162float(h3))));
        __half2 p01 = __floats2half2_rn(v.x, v.y);
        __half2 p23 = __floats2half2_rn(v.z, v.w);
        ((uint2*)g_X16)[i] = make_uint2(*(uint32_t*)&p01, *(uint32_t*)&p23);
        return;
    }
    if (tid < 128) {
        float ang = (float)tid / 64.0f;
        cs[tid] = cospif(ang);
        sn[tid] = sinpif(ang);
    }
    __syncthreads();
    blk -= PREP_SPLIT;
    if (blk < PREP_W1) {
        int idx = blk * 256 + tid;
        int d = idx / N1P_, c = idx - d * N1P_;
        float acc = 0.f;
        if (c < N1_) {
            int region = (c >= 1040) ? 1 : 0;
            int cc = c - region * 1040;
            int hd = cc / 130;
            int u = cc - hd * 130;
            int f = u >> 1;
            const float* w = w_qkv + (size_t)d * 3072 + region * 1024 + hd * 128;
            if ((u & 1) == 0) {
                #pragma unroll 8
                for (int dd = 0; dd < 128; dd++) acc += w[dd] * cs[(f * dd) & 127];
            } else {
                #pragma unroll 8
                for (int dd = 0; dd < 128; dd++) acc -= w[dd] * sn[(f * dd) & 127];
            }
            acc *= SCALE_;
        }
        __half hi = __float2half_rn(acc);
        g_W1T_h16[c * 128 + d] = hi;
        g_W1T_l16[c * 128 + d] = __float2half_rn(acc - __half2float(hi));
        return;
    }
    blk -= PREP_W1;
    if (blk < PREP_W1V) {
        int idx = blk * 256 + tid;
        int d = idx / NK_, k = idx - d * NK_;
        int hd = k / 130;
        int u = k - hd * 130;
        int f = u >> 1;
        const float* w = w_qkv + (size_t)d * 3072 + 2048 + hd * 128;
        float acc = 0.f;
        if ((u & 1) == 0) {
            #pragma unroll 8
            for (int dd = 0; dd < 128; dd++) acc += w[dd] * cs[(f * dd) & 127];
        } else {
            #pragma unroll 8
            for (int dd = 0; dd < 128; dd++) acc -= w[dd] * sn[(f * dd) & 127];
        }
        g_W1v[idx] = acc;
        return;
    }
    blk -= PREP_W1V;
    {
        int idx = blk * 256 + tid;
        int o = idx & 127;
        int r = idx >> 7;
        int x = r % 65;
        int hp = r / 65;
        int p = hp & 1, hd = hp >> 1;
        float acc = 0.f;
        if (p == 0) {
            #pragma unroll 8
            for (int t2 = 0; t2 < 128; t2++)
                acc += cs[(x * t2) & 127] * w_out[(size_t)(hd * 128 + t2) * 128 + o];
            acc *= ((x == 0 || x == 64) ? 1.0f : 2.0f) / 128.0f;
        } else if (x != 0 && x != 64) {
            #pragma unroll 8
            for (int t2 = 0; t2 < 128; t2++)
                acc -= sn[(x * t2) & 127] * w_out[(size_t)(hd * 128 + t2) * 128 + o];
            acc *= 2.0f / 128.0f;
        }
        g_Mout[idx] = acc;
    }
}

// ---------------- GEMM1: fp16 2-pass |X@W1_qk| -> aq, ak [bh][f][e] ----------------
// m256 x n128, 512 thr, 2 stages. Stage 64KB: A 32K @0, Bhi 16K @32768, Blo @49152
#define G1_STG 65536
__device__ __forceinline__ void g1_load(uint32_t sst, int bm, int bn, int k0, int tid) {
    #pragma unroll
    for (int u = tid; u < 2048; u += 512) {
        int r = u >> 3, cb = (u & 7) * 16;
        uint32_t d = swz64(r, cb);
        cp16(sst + d, (const char*)g_X16 + ((size_t)(bm + r) * 128 + k0) * 2 + cb);
    }
    #pragma unroll
    for (int u = tid; u < 1024; u += 512) {
        int r = u >> 3, cb = (u & 7) * 16;
        uint32_t d = swz64(r, cb);
        cp16(sst + 32768 + d, (const char*)g_W1T_h16 + ((size_t)(bn + r) * 128 + k0) * 2 + cb);
        cp16(sst + 49152 + d, (const char*)g_W1T_l16 + ((size_t)(bn + r) * 128 + k0) * 2 + cb);
    }
}

// 2-pass fp16 sweep over one resident [*x64] K-chunk: per k-step 10 ldsm feed 32 mma
__device__ __forceinline__ void mma_chunk64_2p(uint32_t sA, uint32_t sBhi, uint32_t sBlo,
                                               int lane, int wm, int wn, float c[2][8][4]) {
    #pragma unroll
    for (int ks = 0; ks < 4; ks++) {
        int colb = ks * 32 + (lane >> 4) * 16;
        int ar = wm * 32 + (lane & 15);
        uint32_t a[2][4];
        #pragma unroll
        for (int tm = 0; tm < 2; tm++)
            ldsm_x4(a[tm], sA + swz64(ar + tm * 16, colb));
        uint32_t bhi[8][2];
        #pragma unroll
        for (int ng = 0; ng < 4; ng++) {
            int n = wn * 64 + ng * 16 + (lane & 15);
            uint32_t q[4];
            ldsm_x4(q, sBhi + swz64(n, colb));
            bhi[2 * ng][0] = q[0]; bhi[2 * ng + 1][0] = q[1];
            bhi[2 * ng][1] = q[2]; bhi[2 * ng + 1][1] = q[3];
        }
        #pragma unroll
        for (int tm = 0; tm < 2; tm++)
            #pragma unroll
            for (int tn = 0; tn < 8; tn++)
                mma16816_f16(c[tm][tn], a[tm], bhi[tn]);
        uint32_t blo[8][2];
        #pragma unroll
        for (int ng = 0; ng < 4; ng++) {
            int n = wn * 64 + ng * 16 + (lane & 15);
            uint32_t q[4];
            ldsm_x4(q, sBlo + swz64(n, colb));
            blo[2 * ng][0] = q[0]; blo[2 * ng + 1][0] = q[1];
            blo[2 * ng][1] = q[2]; blo[2 * ng + 1][1] = q[3];
        }
        #pragma unroll
        for (int tm = 0; tm < 2; tm++)
            #pragma unroll
            for (int tn = 0; tn < 8; tn++)
                mma16816_f16(c[tm][tn], a[tm], blo[tn]);
    }
}

__global__ void __launch_bounds__(512, 1) gemm1_tc() {
    extern __shared__ char smem[];
    uint32_t sb = smem_u32(smem);
    int tid = threadIdx.x;
    int lane = tid & 31, wid = tid >> 5;
    int wm = wid & 7, wn = wid >> 3;      // 8 x 2 warps over 256 x 128
    int bm = blockIdx.y * 256, bn = blockIdx.x * 128;

    g1_load(sb, bm, bn, 0, tid);  cp_commit();
    g1_load(sb + G1_STG, bm, bn, 64, tid);  cp_commit();

    float c[2][8][4];
    #pragma unroll
    for (int i = 0; i < 2; i++)
        #pragma unroll
        for (int j = 0; j < 8; j++)
            #pragma unroll
            for (int k = 0; k < 4; k++) c[i][j][k] = 0.f;

    cp_wait1();
    __syncthreads();
    mma_chunk64_2p(sb, sb + 32768, sb + 49152, lane, wm, wn, c);
    cp_wait0();
    __syncthreads();
    mma_chunk64_2p(sb + G1_STG, sb + G1_STG + 32768, sb + G1_STG + 49152, lane, wm, wn, c);

    // epilogue: |q|,|k| into [bh][f][e] layout
    int g = lane >> 2, cp2 = (lane & 3) * 2;
    int bloc = (bm >> 11) * 8;               // b*8, constant per CTA
    #pragma unroll
    for (int tn = 0; tn < 8; tn++) {
        int col = bn + wn * 64 + tn * 8 + cp2;   // even
        if (col >= N1_) continue;
        int region = (col >= 1040) ? 1 : 0;
        int cc = col - region * 1040;
        int hd = cc / 130;
        int uu = cc - hd * 130;
        int f = uu >> 1;
        float* base = (region ? g_ak : g_aq) + ((size_t)(bloc + hd) * 65 + f) * 2048;
        #pragma unroll
        for (int tm = 0; tm < 2; tm++)
            #pragma unroll
            for (int hf = 0; hf < 2; hf++) {
                int e = (bm & 2047) + wm * 32 + tm * 16 + hf * 8 + g;
                float re = c[tm][tn][hf * 2], im = c[tm][tn][hf * 2 + 1];
                base[e] = sqrtf(re * re + im * im);
            }
    }
}

// ---------------- att partial: [f][e] layout, packed f32x2 FMA ----------------
__global__ void __launch_bounds__(256) att_partial_kernel() {
    __shared__ float aqs[65 * 66];
    __shared__ float aks[65 * 66];
    int bh = blockIdx.y;
    int chunk = blockIdx.x;
    int tid = threadIdx.x;
    int tx = tid & 15, ty = tid >> 4;
    int xs[5], ys[5];
    #pragma unroll
    for (int i = 0; i < 5; i++) {
        int x = tx + 16 * i; xs[i] = (x < 65) ? x : 0;
        int y = ty + 16 * i; ys[i] = (y < 65) ? y : 0;
    }
    unsigned long long acc2[5][5];
    #pragma unroll
    for (int i = 0; i < 5; i++)
        #pragma unroll
        for (int j = 0; j < 5; j++) acc2[i][j] = 0ull;

    const float* aqsrc = g_aq + (size_t)bh * 65 * 2048;
    const float* aksrc = g_ak + (size_t)bh * 65 * 2048;
    int ebase = chunk * (2048 / EQ_);
    for (int e0 = ebase; e0 < ebase + 2048 / EQ_; e0 += 64) {
        for (int idx = tid; idx < 4160; idx += 256) {
            int f = idx >> 6, r = idx & 63;        // coalesced: e fastest
            size_t gidx = (size_t)f * 2048 + e0 + r;
            aqs[f * 66 + r] = aqsrc[gidx];
            aks[f * 66 + r] = aksrc[gidx];
        }
        __syncthreads();
        #pragma unroll 4
        for (int e2 = 0; e2 < 64; e2 += 2) {
            unsigned long long av[5], bv[5];
            #pragma unroll
            for (int i = 0; i < 5; i++)
                av[i] = *(const unsigned long long*)&aqs[xs[i] * 66 + e2];
            #pragma unroll
            for (int j = 0; j < 5; j++)
                bv[j] = *(const unsigned long long*)&aks[ys[j] * 66 + e2];
            #pragma unroll
            for (int i = 0; i < 5; i++)
                #pragma unroll
                for (int j = 0; j < 5; j++)
                    FMA_F32X2(acc2[i][j], av[i], bv[j]);
        }
        __syncthreads();
    }
    float* dst = g_attp + (size_t)(bh * EQ_ + chunk) * 4225;
    #pragma unroll
    for (int i = 0; i < 5; i++) {
        int x = tx + 16 * i;
        if (x < 65)
            #pragma unroll
            for (int j = 0; j < 5; j++) {
                int y = ty + 16 * j;
                if (y < 65) {
                    float lo = __uint_as_float((uint32_t)(acc2[i][j] & 0xffffffffull));
                    float hi = __uint_as_float((uint32_t)(acc2[i][j] >> 32));
                    dst[x * 65 + y] = lo + hi;
                }
            }
    }
}

// ---------------- softmax: one warp per x-row ----------------
__global__ void __launch_bounds__(256) att_softmax_kernel() {
    int bh = blockIdx.y;
    int warp = threadIdx.x >> 5, lane = threadIdx.x & 31;
    int x = blockIdx.x * 8 + warp;
    if (x >= 65) return;
    const float* p0 = g_attp + (size_t)(bh * EQ_) * 4225 + x * 65;
    float v[3];
    float m = -3.4e38f;
    #pragma unroll
    for (int t = 0; t < 3; t++) {
        int y = lane + t * 32;
        float s = 0.f;
        if (y < 65) {
            #pragma unroll
            for (int q = 0; q < EQ_; q++) s += p0[q * 4225 + y];
        } else s = -3.4e38f;
        v[t] = s;
        m = fmaxf(m, s);
    }
    #pragma unroll
    for (int o = 16; o; o >>= 1) m = fmaxf(m, __shfl_xor_sync(0xffffffffu, m, o));
    float sum = 0.f;
    #pragma unroll
    for (int t = 0; t < 3; t++) {
        int y = lane + t * 32;
        if (y < 65) {
            v[t] = expf(v[t] - m);
            sum += v[t];
        }
    }
    #pragma unroll
    for (int o = 16; o; o >>= 1) sum += __shfl_xor_sync(0xffffffffu, sum, o);
    float inv = 1.0f / sum;
    float* dst = g_att + (size_t)bh * 4225 + x * 65;
    #pragma unroll
    for (int t = 0; t < 3; t++) {
        int y = lane + t * 32;
        if (y < 65) dst[y] = v[t] * inv;
    }
}

// ---------------- build C_b ----------------
__global__ void __launch_bounds__(256) build_c_kernel() {
    extern __shared__ float csm[];
    float* att_s = csm;
    float* mout_s = csm + 4225;
    int blk = blockIdx.x;                    // b*16 + h*2 + p
    int b = blk >> 4;
    int hp = blk & 15;
    int hd = hp >> 1, p = hp & 1;
    int tid = threadIdx.x;
    int bh = b * 8 + hd;
    for (int idx = tid; idx < 4225; idx += 256)
        att_s[idx] = g_att[(size_t)bh * 4225 + idx];
    for (int idx = tid; idx < 8320; idx += 256)
        mout_s[idx] = g_Mout[(size_t)hp * 8320 + idx];
    __syncthreads();
    for (int idx = tid; idx < 8320; idx += 256) {
        int o = idx / 65, y = idx - o * 65;
        float acc = 0.f;
        #pragma unroll 5
        for (int x = 0; x < 65; x++)
            acc += att_s[x * 65 + y] * mout_s[x * 128 + o];
        int k = hd * 130 + 2 * y + p;
        g_C[((size_t)b * NK_ + k) * 128 + o] = acc;
    }
}

// ---------------- build D_b = W1v @ C_b, split to DT hi/lo ----------------
__global__ void __launch_bounds__(256) build_d_kernel() {
    __shared__ float Wvs[128 * 65];
    __shared__ float Cs[65 * 32];
    int b = blockIdx.x;
    int o0 = blockIdx.y * 32;
    int tid = threadIdx.x;
    int ol = tid & 31, dg = tid >> 5;
    float acc[16];
    #pragma unroll
    for (int i = 0; i < 16; i++) acc[i] = 0.f;

    for (int k0 = 0; k0 < NK_; k0 += 65) {
        __syncthreads();
        for (int u = tid; u < 8320; u += 256) {
            int d = u / 65, kk = u - d * 65;
            Wvs[u] = g_W1v[(size_t)d * NK_ + k0 + kk];
        }
        for (int u = tid; u < 2080; u += 256) {
            int kk = u >> 5, oo = u & 31;
            Cs[u] = g_C[((size_t)b * NK_ + k0 + kk) * 128 + o0 + oo];
        }
        __syncthreads();
        #pragma unroll 5
        for (int kk = 0; kk < 65; kk++) {
            float cv = Cs[kk * 32 + ol];
            #pragma unroll
            for (int i = 0; i < 16; i++)
                acc[i] += Wvs[(dg + 8 * i) * 65 + kk] * cv;
        }
    }
    #pragma unroll
    for (int i = 0; i < 16; i++) {
        int d = dg + 8 * i;
        __nv_bfloat16 hi = __float2bfloat16(acc[i]);
        size_t off = ((size_t)b * 128 + o0 + ol) * 128 + d;
        g_DThi[off] = hi;
        g_DTlo[off] = __float2bfloat16(acc[i] - __bfloat162float(hi));
    }
}

// ---------------- final GEMM: out = X @ D_b + bias (bf16 3-pass, 2-group pipelined) ----------------
#define FG_AHI 0
#define FG_ALO 65536
#define FG_BHI 131072
#define FG_BLO 163840
#define FG_TOT 196608

// bf16 3-pass sweep over one resident 64-wide K-chunk, warp grid 8x2
__device__ __forceinline__ void mma_chunk64_3p(uint32_t sAhi, uint32_t sAlo,
                                               uint32_t sBhi, uint32_t sBlo,
                                               int lane, int wm, int wn, float c[2][8][4]) {
    #pragma unroll
    for (int ks = 0; ks < 4; ks++) {
        int colb = ks * 32 + (lane >> 4) * 16;
        int ar = wm * 32 + (lane & 15);
        uint32_t ahi[2][4], alo[2][4];
        #pragma unroll
        for (int tm = 0; tm < 2; tm++)
            ldsm_x4(ahi[tm], sAhi + swz64(ar + tm * 16, colb));
        uint32_t bhi[8][2], blo[8][2];
        #pragma unroll
        for (int ng = 0; ng < 4; ng++) {
            int n = wn * 64 + ng * 16 + (lane & 15);
            uint32_t q[4];
            ldsm_x4(q, sBhi + swz64(n, colb));
            bhi[2 * ng][0] = q[0]; bhi[2 * ng + 1][0] = q[1];
            bhi[2 * ng][1] = q[2]; bhi[2 * ng + 1][1] = q[3];
        }
        #pragma unroll
        for (int tm = 0; tm < 2; tm++)
            #pragma unroll
            for (int tn = 0; tn < 8; tn++)
                mma16816_bf(c[tm][tn], ahi[tm], bhi[tn]);
        #pragma unroll
        for (int ng = 0; ng < 4; ng++) {
            int n = wn * 64 + ng * 16 + (lane & 15);
            uint32_t q[4];
            ldsm_x4(q, sBlo + swz64(n, colb));
            blo[2 * ng][0] = q[0]; blo[2 * ng + 1][0] = q[1];
            blo[2 * ng][1] = q[2]; blo[2 * ng + 1][1] = q[3];
        }
        #pragma unroll
        for (int tm = 0; tm < 2; tm++)
            #pragma unroll
            for (int tn = 0; tn < 8; tn++)
                mma16816_bf(c[tm][tn], ahi[tm], blo[tn]);
        #pragma unroll
        for (int tm = 0; tm < 2; tm++)
            ldsm_x4(alo[tm], sAlo + swz64(ar + tm * 16, colb));
        #pragma unroll
        for (int tm = 0; tm < 2; tm++)
            #pragma unroll
            for (int tn = 0; tn < 8; tn++)
                mma16816_bf(c[tm][tn], alo[tm], bhi[tn]);
    }
}

__global__ void __launch_bounds__(512, 1) final_gemm(float* __restrict__ out,
                                                     const float* __restrict__ bias) {
    extern __shared__ char smem[];
    uint32_t sb = smem_u32(smem);
    int tid = threadIdx.x;
    int lane = tid & 31, wid = tid >> 5;
    int wm = wid & 7, wn = wid >> 3;
    int bm = blockIdx.x * 256;
    int b = bm >> 11;

    #pragma unroll
    for (int ch = 0; ch < 2; ch++) {
        #pragma unroll
        for (int u = tid; u < 2048; u += 512) {
            int r = u >> 3, cb = (u & 7) * 16;
            uint32_t d = ch * 32768 + swz64(r, cb);
            size_t src = (size_t)(bm + r) * 256 + ch * 128 + cb;
            cp16(sb + FG_AHI + d, (const char*)g_Xhi + src);
            cp16(sb + FG_ALO + d, (const char*)g_Xlo + src);
        }
        #pragma unroll
        for (int u = tid; u < 1024; u += 512) {
            int r = u >> 3, cb = (u & 7) * 16;
            uint32_t d = ch * 16384 + swz64(r, cb);
            size_t src = ((size_t)(b * 128 + r)) * 256 + ch * 128 + cb;
            cp16(sb + FG_BHI + d, (const char*)g_DThi + src);
            cp16(sb + FG_BLO + d, (const char*)g_DTlo + src);
        }
        cp_commit();
    }

    float c[2][8][4];
    #pragma unroll
    for (int i = 0; i < 2; i++)
        #pragma unroll
        for (int j = 0; j < 8; j++)
            #pragma unroll
            for (int k = 0; k < 4; k++) c[i][j][k] = 0.f;

    cp_wait1();
    __syncthreads();
    mma_chunk64_3p(sb + FG_AHI, sb + FG_ALO, sb + FG_BHI, sb + FG_BLO, lane, wm, wn, c);
    cp_wait0();
    __syncthreads();
    mma_chunk64_3p(sb + FG_AHI + 32768, sb + FG_ALO + 32768,
                   sb + FG_BHI + 16384, sb + FG_BLO + 16384, lane, wm, wn, c);

    int g = lane >> 2, cp2 = (lane & 3) * 2;
    #pragma unroll
    for (int tm = 0; tm < 2; tm++)
        #pragma unroll
        for (int hf = 0; hf < 2; hf++) {
            size_t row = (size_t)bm + wm * 32 + tm * 16 + hf * 8 + g;
            float* dst = out + row * 128;
            #pragma unroll
            for (int tn = 0; tn < 8; tn++) {
                int col = wn * 64 + tn * 8 + cp2;
                float2 bv = *(const float2*)(bias + col);
                *(float2*)(dst + col) = make_float2(c[tm][tn][hf * 2] + bv.x,
                                                    c[tm][tn][hf * 2 + 1] + bv.y);
            }
        }
}

// ---------------- launch ----------------
extern "C" void kernel_launch(void* const* d_in, const int* in_sizes, int n_in,
                              void* d_out, int out_size) {
    const float* x     = (const float*)d_in[0];
    const float* w_qkv = (const float*)d_in[1];
    const float* w_out = (const float*)d_in[2];
    const float* b_out = (const float*)d_in[3];
    float* out = (float*)d_out;

    cudaFuncSetAttribute(gemm1_tc, cudaFuncAttributeMaxDynamicSharedMemorySize, 2 * G1_STG);
    cudaFuncSetAttribute(final_gemm, cudaFuncAttributeMaxDynamicSharedMemorySize, FG_TOT);
    cudaFuncSetAttribute(build_c_kernel, cudaFuncAttributeMaxDynamicSharedMemorySize,
                         (4225 + 8320) * 4);

    prep_kernel<<<PREP_TOTAL, 256>>>(x, w_qkv, w_out);
    gemm1_tc<<<dim3(N1P_ / 128, ROWS_ / 256), 512, 2 * G1_STG>>>();
    att_partial_kernel<<<dim3(EQ_, B_ * H_), 256>>>();
    att_softmax_kernel<<<dim3(9, B_ * H_), 256>>>();
    build_c_kernel<<<B_ * H_ * 2, 256, (4225 + 8320) * 4>>>();
    build_d_kernel<<<dim3(B_, 4), 256>>>();
    final_gemm<<<ROWS_ / 256, 512, FG_TOT>>>(out, b_out);
}

// round 14
// speedup vs baseline: 1.8612x; 1.0949x over previous
#include <cuda_runtime.h>
#include <cuda_bf16.h>
#include <cuda_fp16.h>
#include <cstdint>
#include <math.h>

// Problem constants
#define B_    16
#define N_    2048
#define D_    128
#define H_    8
#define F_    65
#define ROWS_ 32768
#define N1_   2080       // q,k: 2 regions * 8 heads * 130 (re/im interleaved u=2f+p)
#define N1P_  2176       // 17 n-tiles of 128
#define NK_   1040
#define SCALE_ (1.0f/65.0f)
#define EQ_   8

// ---------------- scratch (static device, no allocation) ----------------
__device__ __half g_X16[(size_t)ROWS_ * D_];          // single fp16 X (gemm1 + final)
__device__ __half g_W1T_h16[N1P_ * D_];               // single fp16 folded q,k weights
__device__ float g_W1v[D_ * NK_];
__device__ float g_Mout[H_ * 2 * F_ * D_];            // [h][p][x][o]
__device__ float g_aq[(size_t)B_ * H_ * F_ * N_];     // [bh][f][e]
__device__ float g_ak[(size_t)B_ * H_ * F_ * N_];
__device__ float g_attp[B_ * H_ * EQ_ * F_ * F_];
__device__ float g_att[B_ * H_ * F_ * F_];
__device__ float g_C[B_ * NK_ * D_];                  // [b][k][o]
__device__ __half g_DTh16[B_ * D_ * D_];              // [b][o][d] fp16 hi/lo
__device__ __half g_DTl16[B_ * D_ * D_];

// ---------------- helpers ----------------
__device__ __forceinline__ uint32_t smem_u32(const void* p) {
    uint32_t a;
    asm("{ .reg .u64 t; cvta.to.shared.u64 t, %1; cvt.u32.u64 %0, t; }" : "=r"(a) : "l"(p));
    return a;
}
__device__ __forceinline__ void ldsm_x4(uint32_t* r, uint32_t addr) {
    asm volatile("ldmatrix.sync.aligned.m8n8.x4.shared.b16 {%0,%1,%2,%3}, [%4];"
                 : "=r"(r[0]), "=r"(r[1]), "=r"(r[2]), "=r"(r[3]) : "r"(addr));
}
__device__ __forceinline__ void mma16816_f16(float* c, const uint32_t* a, const uint32_t* b) {
    asm volatile("mma.sync.aligned.m16n8k16.row.col.f32.f16.f16.f32 "
                 "{%0,%1,%2,%3}, {%4,%5,%6,%7}, {%8,%9}, {%0,%1,%2,%3};"
                 : "+f"(c[0]), "+f"(c[1]), "+f"(c[2]), "+f"(c[3])
                 : "r"(a[0]), "r"(a[1]), "r"(a[2]), "r"(a[3]), "r"(b[0]), "r"(b[1]));
}
#define FMA_F32X2(d, a, b) \
    asm("fma.rn.f32x2 %0, %1, %2, %0;" : "+l"(d) : "l"(a), "l"(b))
// swizzled offset within a [rows][64 x 16bit] tile (row = 128 bytes)
__device__ __forceinline__ uint32_t swz64(int row, int colbyte) {
    return (uint32_t)(row * 128 + (colbyte ^ ((row & 7) << 4)));
}
__device__ __forceinline__ void cp16(uint32_t dst, const void* src) {
    asm volatile("cp.async.cg.shared.global [%0], [%1], 16;" :: "r"(dst), "l"(src));
}
__device__ __forceinline__ void cp_commit() { asm volatile("cp.async.commit_group;"); }
__device__ __forceinline__ void cp_wait0() { asm volatile("cp.async.wait_group 0;" ::: "memory"); }
__device__ __forceinline__ void cp_wait1() { asm volatile("cp.async.wait_group 1;" ::: "memory"); }

// ---------------- merged prep ----------------
#define PREP_SPLIT  4096
#define PREP_W1     1088
#define PREP_W1V    520
#define PREP_MOUT   520
#define PREP_TOTAL  (PREP_SPLIT + PREP_W1 + PREP_W1V + PREP_MOUT)

__global__ void __launch_bounds__(256) prep_kernel(const float* __restrict__ X,
                                                   const float* __restrict__ w_qkv,
                                                   const float* __restrict__ w_out) {
    __shared__ float cs[128], sn[128];
    int tid = threadIdx.x;
    int blk = blockIdx.x;
    if (blk < PREP_SPLIT) {
        size_t i = (size_t)blk * 256 + tid;
        float4 v = ((const float4*)X)[i];
        __half2 p01 = __floats2half2_rn(v.x, v.y);
        __half2 p23 = __floats2half2_rn(v.z, v.w);
        ((uint2*)g_X16)[i] = make_uint2(*(uint32_t*)&p01, *(uint32_t*)&p23);
        return;
    }
    if (tid < 128) {
        float ang = (float)tid / 64.0f;
        cs[tid] = cospif(ang);
        sn[tid] = sinpif(ang);
    }
    __syncthreads();
    blk -= PREP_SPLIT;
    if (blk < PREP_W1) {
        int idx = blk * 256 + tid;
        int d = idx / N1P_, c = idx - d * N1P_;
        float acc = 0.f;
        if (c < N1_) {
            int region = (c >= 1040) ? 1 : 0;
            int cc = c - region * 1040;
            int hd = cc / 130;
            int u = cc - hd * 130;
            int f = u >> 1;
            const float* w = w_qkv + (size_t)d * 3072 + region * 1024 + hd * 128;
            if ((u & 1) == 0) {
                #pragma unroll 8
                for (int dd = 0; dd < 128; dd++) acc += w[dd] * cs[(f * dd) & 127];
            } else {
                #pragma unroll 8
                for (int dd = 0; dd < 128; dd++) acc -= w[dd] * sn[(f * dd) & 127];
            }
            acc *= SCALE_;
        }
        g_W1T_h16[c * 128 + d] = __float2half_rn(acc);
        return;
    }
    blk -= PREP_W1;
    if (blk < PREP_W1V) {
        int idx = blk * 256 + tid;
        int d = idx / NK_, k = idx - d * NK_;
        int hd = k / 130;
        int u = k - hd * 130;
        int f = u >> 1;
        const float* w = w_qkv + (size_t)d * 3072 + 2048 + hd * 128;
        float acc = 0.f;
        if ((u & 1) == 0) {
            #pragma unroll 8
            for (int dd = 0; dd < 128; dd++) acc += w[dd] * cs[(f * dd) & 127];
        } else {
            #pragma unroll 8
            for (int dd = 0; dd < 128; dd++) acc -= w[dd] * sn[(f * dd) & 127];
        }
        g_W1v[idx] = acc;
        return;
    }
    blk -= PREP_W1V;
    {
        int idx = blk * 256 + tid;
        int o = idx & 127;
        int r = idx >> 7;
        int x = r % 65;
        int hp = r / 65;
        int p = hp & 1, hd = hp >> 1;
        float acc = 0.f;
        if (p == 0) {
            #pragma unroll 8
            for (int t2 = 0; t2 < 128; t2++)
                acc += cs[(x * t2) & 127] * w_out[(size_t)(hd * 128 + t2) * 128 + o];
            acc *= ((x == 0 || x == 64) ? 1.0f : 2.0f) / 128.0f;
        } else if (x != 0 && x != 64) {
            #pragma unroll 8
            for (int t2 = 0; t2 < 128; t2++)
                acc -= sn[(x * t2) & 127] * w_out[(size_t)(hd * 128 + t2) * 128 + o];
            acc *= 2.0f / 128.0f;
        }
        g_Mout[idx] = acc;
    }
}

// ---------------- single-pass fp16 sweep over one resident [*x64] K-chunk ----------------
// per k-step: 6 ldsm feed 16 mma
__device__ __forceinline__ void mma_chunk64_1p(uint32_t sA, uint32_t sB,
                                               int lane, int wm, int wn, float c[2][8][4]) {
    #pragma unroll
    for (int ks = 0; ks < 4; ks++) {
        int colb = ks * 32 + (lane >> 4) * 16;
        int ar = wm * 32 + (lane & 15);
        uint32_t a[2][4];
        #pragma unroll
        for (int tm = 0; tm < 2; tm++)
            ldsm_x4(a[tm], sA + swz64(ar + tm * 16, colb));
        uint32_t b[8][2];
        #pragma unroll
        for (int ng = 0; ng < 4; ng++) {
            int n = wn * 64 + ng * 16 + (lane & 15);
            uint32_t q[4];
            ldsm_x4(q, sB + swz64(n, colb));
            b[2 * ng][0] = q[0]; b[2 * ng + 1][0] = q[1];
            b[2 * ng][1] = q[2]; b[2 * ng + 1][1] = q[3];
        }
        #pragma unroll
        for (int tm = 0; tm < 2; tm++)
            #pragma unroll
            for (int tn = 0; tn < 8; tn++)
                mma16816_f16(c[tm][tn], a[tm], b[tn]);
    }
}

// 2-pass fp16 sweep (A single, B hi/lo): per k-step 10 ldsm feed 32 mma
__device__ __forceinline__ void mma_chunk64_2p(uint32_t sA, uint32_t sBhi, uint32_t sBlo,
                                               int lane, int wm, int wn, float c[2][8][4]) {
    #pragma unroll
    for (int ks = 0; ks < 4; ks++) {
        int colb = ks * 32 + (lane >> 4) * 16;
        int ar = wm * 32 + (lane & 15);
        uint32_t a[2][4];
        #pragma unroll
        for (int tm = 0; tm < 2; tm++)
            ldsm_x4(a[tm], sA + swz64(ar + tm * 16, colb));
        uint32_t bhi[8][2];
        #pragma unroll
        for (int ng = 0; ng < 4; ng++) {
            int n = wn * 64 + ng * 16 + (lane & 15);
            uint32_t q[4];
            ldsm_x4(q, sBhi + swz64(n, colb));
            bhi[2 * ng][0] = q[0]; bhi[2 * ng + 1][0] = q[1];
            bhi[2 * ng][1] = q[2]; bhi[2 * ng + 1][1] = q[3];
        }
        #pragma unroll
        for (int tm = 0; tm < 2; tm++)
            #pragma unroll
            for (int tn = 0; tn < 8; tn++)
                mma16816_f16(c[tm][tn], a[tm], bhi[tn]);
        uint32_t blo[8][2];
        #pragma unroll
        for (int ng = 0; ng < 4; ng++) {
            int n = wn * 64 + ng * 16 + (lane & 15);
            uint32_t q[4];
            ldsm_x4(q, sBlo + swz64(n, colb));
            blo[2 * ng][0] = q[0]; blo[2 * ng + 1][0] = q[1];
            blo[2 * ng][1] = q[2]; blo[2 * ng + 1][1] = q[3];
        }
        #pragma unroll
        for (int tm = 0; tm < 2; tm++)
            #pragma unroll
            for (int tn = 0; tn < 8; tn++)
                mma16816_f16(c[tm][tn], a[tm], blo[tn]);
    }
}

// ---------------- GEMM1: single-pass fp16 |X@W1_qk| -> aq, ak [bh][f][e] ----------------
// m256 x n128, 512 thr, 2 stages. Stage 48KB: A 32K @0, B 16K @32768
#define G1_STG 49152
__device__ __forceinline__ void g1_load(uint32_t sst, int bm, int bn, int k0, int tid) {
    #pragma unroll
    for (int u = tid; u < 2048; u += 512) {
        int r = u >> 3, cb = (u & 7) * 16;
        uint32_t d = swz64(r, cb);
        cp16(sst + d, (const char*)g_X16 + ((size_t)(bm + r) * 128 + k0) * 2 + cb);
    }
    #pragma unroll
    for (int u = tid; u < 1024; u += 512) {
        int r = u >> 3, cb = (u & 7) * 16;
        uint32_t d = swz64(r, cb);
        cp16(sst + 32768 + d, (const char*)g_W1T_h16 + ((size_t)(bn + r) * 128 + k0) * 2 + cb);
    }
}

__global__ void __launch_bounds__(512, 1) gemm1_tc() {
    extern __shared__ char smem[];
    uint32_t sb = smem_u32(smem);
    int tid = threadIdx.x;
    int lane = tid & 31, wid = tid >> 5;
    int wm = wid & 7, wn = wid >> 3;      // 8 x 2 warps over 256 x 128
    int bm = blockIdx.y * 256, bn = blockIdx.x * 128;

    g1_load(sb, bm, bn, 0, tid);  cp_commit();
    g1_load(sb + G1_STG, bm, bn, 64, tid);  cp_commit();

    float c[2][8][4];
    #pragma unroll
    for (int i = 0; i < 2; i++)
        #pragma unroll
        for (int j = 0; j < 8; j++)
            #pragma unroll
            for (int k = 0; k < 4; k++) c[i][j][k] = 0.f;

    cp_wait1();
    __syncthreads();
    mma_chunk64_1p(sb, sb + 32768, lane, wm, wn, c);
    cp_wait0();
    __syncthreads();
    mma_chunk64_1p(sb + G1_STG, sb + G1_STG + 32768, lane, wm, wn, c);

    // epilogue: |q|,|k| into [bh][f][e] layout
    int g = lane >> 2, cp2 = (lane & 3) * 2;
    int bloc = (bm >> 11) * 8;               // b*8, constant per CTA
    #pragma unroll
    for (int tn = 0; tn < 8; tn++) {
        int col = bn + wn * 64 + tn * 8 + cp2;   // even
        if (col >= N1_) continue;
        int region = (col >= 1040) ? 1 : 0;
        int cc = col - region * 1040;
        int hd = cc / 130;
        int uu = cc - hd * 130;
        int f = uu >> 1;
        float* base = (region ? g_ak : g_aq) + ((size_t)(bloc + hd) * 65 + f) * 2048;
        #pragma unroll
        for (int tm = 0; tm < 2; tm++)
            #pragma unroll
            for (int hf = 0; hf < 2; hf++) {
                int e = (bm & 2047) + wm * 32 + tm * 16 + hf * 8 + g;
                float re = c[tm][tn][hf * 2], im = c[tm][tn][hf * 2 + 1];
                base[e] = sqrtf(re * re + im * im);
            }
    }
}

// ---------------- att partial: [f][e] layout, packed f32x2 FMA ----------------
__global__ void __launch_bounds__(256) att_partial_kernel() {
    __shared__ float aqs[65 * 66];
    __shared__ float aks[65 * 66];
    int bh = blockIdx.y;
    int chunk = blockIdx.x;
    int tid = threadIdx.x;
    int tx = tid & 15, ty = tid >> 4;
    int xs[5], ys[5];
    #pragma unroll
    for (int i = 0; i < 5; i++) {
        int x = tx + 16 * i; xs[i] = (x < 65) ? x : 0;
        int y = ty + 16 * i; ys[i] = (y < 65) ? y : 0;
    }
    unsigned long long acc2[5][5];
    #pragma unroll
    for (int i = 0; i < 5; i++)
        #pragma unroll
        for (int j = 0; j < 5; j++) acc2[i][j] = 0ull;

    const float* aqsrc = g_aq + (size_t)bh * 65 * 2048;
    const float* aksrc = g_ak + (size_t)bh * 65 * 2048;
    int ebase = chunk * (2048 / EQ_);
    for (int e0 = ebase; e0 < ebase + 2048 / EQ_; e0 += 64) {
        for (int idx = tid; idx < 4160; idx += 256) {
            int f = idx >> 6, r = idx & 63;        // coalesced: e fastest
            size_t gidx = (size_t)f * 2048 + e0 + r;
            aqs[f * 66 + r] = aqsrc[gidx];
            aks[f * 66 + r] = aksrc[gidx];
        }
        __syncthreads();
        #pragma unroll 4
        for (int e2 = 0; e2 < 64; e2 += 2) {
            unsigned long long av[5], bv[5];
            #pragma unroll
            for (int i = 0; i < 5; i++)
                av[i] = *(const unsigned long long*)&aqs[xs[i] * 66 + e2];
            #pragma unroll
            for (int j = 0; j < 5; j++)
                bv[j] = *(const unsigned long long*)&aks[ys[j] * 66 + e2];
            #pragma unroll
            for (int i = 0; i < 5; i++)
                #pragma unroll
                for (int j = 0; j < 5; j++)
                    FMA_F32X2(acc2[i][j], av[i], bv[j]);
        }
        __syncthreads();
    }
    float* dst = g_attp + (size_t)(bh * EQ_ + chunk) * 4225;
    #pragma unroll
    for (int i = 0; i < 5; i++) {
        int x = tx + 16 * i;
        if (x < 65)
            #pragma unroll
            for (int j = 0; j < 5; j++) {
                int y = ty + 16 * j;
                if (y < 65) {
                    float lo = __uint_as_float((uint32_t)(acc2[i][j] & 0xffffffffull));
                    float hi = __uint_as_float((uint32_t)(acc2[i][j] >> 32));
                    dst[x * 65 + y] = lo + hi;
                }
            }
    }
}

// ---------------- softmax: one warp per x-row ----------------
__global__ void __launch_bounds__(256) att_softmax_kernel() {
    int bh = blockIdx.y;
    int warp = threadIdx.x >> 5, lane = threadIdx.x & 31;
    int x = blockIdx.x * 8 + warp;
    if (x >= 65) return;
    const float* p0 = g_attp + (size_t)(bh * EQ_) * 4225 + x * 65;
    float v[3];
    float m = -3.4e38f;
    #pragma unroll
    for (int t = 0; t < 3; t++) {
        int y = lane + t * 32;
        float s = 0.f;
        if (y < 65) {
            #pragma unroll
            for (int q = 0; q < EQ_; q++) s += p0[q * 4225 + y];
        } else s = -3.4e38f;
        v[t] = s;
        m = fmaxf(m, s);
    }
    #pragma unroll
    for (int o = 16; o; o >>= 1) m = fmaxf(m, __shfl_xor_sync(0xffffffffu, m, o));
    float sum = 0.f;
    #pragma unroll
    for (int t = 0; t < 3; t++) {
        int y = lane + t * 32;
        if (y < 65) {
            v[t] = expf(v[t] - m);
            sum += v[t];
        }
    }
    #pragma unroll
    for (int o = 16; o; o >>= 1) sum += __shfl_xor_sync(0xffffffffu, sum, o);
    float inv = 1.0f / sum;
    float* dst = g_att + (size_t)bh * 4225 + x * 65;
    #pragma unroll
    for (int t = 0; t < 3; t++) {
        int y = lane + t * 32;
        if (y < 65) dst[y] = v[t] * inv;
    }
}

// ---------------- build C_b ----------------
__global__ void __launch_bounds__(256) build_c_kernel() {
    extern __shared__ float csm[];
    float* att_s = csm;
    float* mout_s = csm + 4225;
    int blk = blockIdx.x;                    // b*16 + h*2 + p
    int b = blk >> 4;
    int hp = blk & 15;
    int hd = hp >> 1, p = hp & 1;
    int tid = threadIdx.x;
    int bh = b * 8 + hd;
    for (int idx = tid; idx < 4225; idx += 256)
        att_s[idx] = g_att[(size_t)bh * 4225 + idx];
    for (int idx = tid; idx < 8320; idx += 256)
        mout_s[idx] = g_Mout[(size_t)hp * 8320 + idx];
    __syncthreads();
    for (int idx = tid; idx < 8320; idx += 256) {
        int o = idx / 65, y = idx - o * 65;
        float acc = 0.f;
        #pragma unroll 5
        for (int x = 0; x < 65; x++)
            acc += att_s[x * 65 + y] * mout_s[x * 128 + o];
        int k = hd * 130 + 2 * y + p;
        g_C[((size_t)b * NK_ + k) * 128 + o] = acc;
    }
}

// ---------------- build D_b = W1v @ C_b, split to fp16 hi/lo ----------------
__global__ void __launch_bounds__(256) build_d_kernel() {
    __shared__ float Wvs[128 * 65];
    __shared__ float Cs[65 * 32];
    int b = blockIdx.x;
    int o0 = blockIdx.y * 32;
    int tid = threadIdx.x;
    int ol = tid & 31, dg = tid >> 5;
    float acc[16];
    #pragma unroll
    for (int i = 0; i < 16; i++) acc[i] = 0.f;

    for (int k0 = 0; k0 < NK_; k0 += 65) {
        __syncthreads();
        for (int u = tid; u < 8320; u += 256) {
            int d = u / 65, kk = u - d * 65;
            Wvs[u] = g_W1v[(size_t)d * NK_ + k0 + kk];
        }
        for (int u = tid; u < 2080; u += 256) {
            int kk = u >> 5, oo = u & 31;
            Cs[u] = g_C[((size_t)b * NK_ + k0 + kk) * 128 + o0 + oo];
        }
        __syncthreads();
        #pragma unroll 5
        for (int kk = 0; kk < 65; kk++) {
            float cv = Cs[kk * 32 + ol];
            #pragma unroll
            for (int i = 0; i < 16; i++)
                acc[i] += Wvs[(dg + 8 * i) * 65 + kk] * cv;
        }
    }
    #pragma unroll
    for (int i = 0; i < 16; i++) {
        int d = dg + 8 * i;
        __half hi = __float2half_rn(acc[i]);
        size_t off = ((size_t)b * 128 + o0 + ol) * 128 + d;
        g_DTh16[off] = hi;
        g_DTl16[off] = __float2half_rn(acc[i] - __half2float(hi));
    }
}

// ---------------- final GEMM: out = X16 @ D_b (fp16 2-pass) + bias ----------------
// m256, K=128. SMEM: A 2x32K @0, Bhi 2x16K @65536, Blo 2x16K @98304 = 128K total
#define FG_A   0
#define FG_BHI 65536
#define FG_BLO 98304
#define FG_TOT 131072
__global__ void __launch_bounds__(512, 1) final_gemm(float* __restrict__ out,
                                                     const float* __restrict__ bias) {
    extern __shared__ char smem[];
    uint32_t sb = smem_u32(smem);
    int tid = threadIdx.x;
    int lane = tid & 31, wid = tid >> 5;
    int wm = wid & 7, wn = wid >> 3;
    int bm = blockIdx.x * 256;
    int b = bm >> 11;

    // two commit groups (K-chunk 0, then 1) so mma on ch0 overlaps ch1 load
    #pragma unroll
    for (int ch = 0; ch < 2; ch++) {
        #pragma unroll
        for (int u = tid; u < 2048; u += 512) {
            int r = u >> 3, cb = (u & 7) * 16;
            uint32_t d = ch * 32768 + swz64(r, cb);
            size_t src = (size_t)(bm + r) * 256 + ch * 128 + cb;
            cp16(sb + FG_A + d, (const char*)g_X16 + src);
        }
        #pragma unroll
        for (int u = tid; u < 1024; u += 512) {
            int r = u >> 3, cb = (u & 7) * 16;
            uint32_t d = ch * 16384 + swz64(r, cb);
            size_t src = ((size_t)(b * 128 + r)) * 256 + ch * 128 + cb;
            cp16(sb + FG_BHI + d, (const char*)g_DTh16 + src);
            cp16(sb + FG_BLO + d, (const char*)g_DTl16 + src);
        }
        cp_commit();
    }

    float c[2][8][4];
    #pragma unroll
    for (int i = 0; i < 2; i++)
        #pragma unroll
        for (int j = 0; j < 8; j++)
            #pragma unroll
            for (int k = 0; k < 4; k++) c[i][j][k] = 0.f;

    cp_wait1();
    __syncthreads();
    mma_chunk64_2p(sb + FG_A, sb + FG_BHI, sb + FG_BLO, lane, wm, wn, c);
    cp_wait0();
    __syncthreads();
    mma_chunk64_2p(sb + FG_A + 32768, sb + FG_BHI + 16384, sb + FG_BLO + 16384,
                   lane, wm, wn, c);

    int g = lane >> 2, cp2 = (lane & 3) * 2;
    #pragma unroll
    for (int tm = 0; tm < 2; tm++)
        #pragma unroll
        for (int hf = 0; hf < 2; hf++) {
            size_t row = (size_t)bm + wm * 32 + tm * 16 + hf * 8 + g;
            float* dst = out + row * 128;
            #pragma unroll
            for (int tn = 0; tn < 8; tn++) {
                int col = wn * 64 + tn * 8 + cp2;
                float2 bv = *(const float2*)(bias + col);
                *(float2*)(dst + col) = make_float2(c[tm][tn][hf * 2] + bv.x,
                                                    c[tm][tn][hf * 2 + 1] + bv.y);
            }
        }
}

// ---------------- launch ----------------
extern "C" void kernel_launch(void* const* d_in, const int* in_sizes, int n_in,
                              void* d_out, int out_size) {
    const float* x     = (const float*)d_in[0];
    const float* w_qkv = (const float*)d_in[1];
    const float* w_out = (const float*)d_in[2];
    const float* b_out = (const float*)d_in[3];
    float* out = (float*)d_out;

    cudaFuncSetAttribute(gemm1_tc, cudaFuncAttributeMaxDynamicSharedMemorySize, 2 * G1_STG);
    cudaFuncSetAttribute(final_gemm, cudaFuncAttributeMaxDynamicSharedMemorySize, FG_TOT);
    cudaFuncSetAttribute(build_c_kernel, cudaFuncAttributeMaxDynamicSharedMemorySize,
                         (4225 + 8320) * 4);

    prep_kernel<<<PREP_TOTAL, 256>>>(x, w_qkv, w_out);
    gemm1_tc<<<dim3(N1P_ / 128, ROWS_ / 256), 512, 2 * G1_STG>>>();
    att_partial_kernel<<<dim3(EQ_, B_ * H_), 256>>>();
    att_softmax_kernel<<<dim3(9, B_ * H_), 256>>>();
    build_c_kernel<<<B_ * H_ * 2, 256, (4225 + 8320) * 4>>>();
    build_d_kernel<<<dim3(B_, 4), 256>>>();
    final_gemm<<<ROWS_ / 256, 512, FG_TOT>>>(out, b_out);
}

// round 15
// speedup vs baseline: 1.9038x; 1.0229x over previous
#include <cuda_runtime.h>
#include <cuda_bf16.h>
#include <cuda_fp16.h>
#include <cstdint>
#include <math.h>

// Problem constants
#define B_    16
#define N_    2048
#define D_    128
#define H_    8
#define F_    65
#define ROWS_ 32768
#define N1_   2080       // q,k: 2 regions * 8 heads * 130 (re/im interleaved u=2f+p)
#define N1P_  2176       // 17 n-tiles of 128
#define NK_   1040
#define SCALE_ (1.0f/65.0f)
#define EQ_   8

// ---------------- scratch (static device, no allocation) ----------------
__device__ __half g_X16[(size_t)ROWS_ * D_];          // single fp16 X (gemm1 + final)
__device__ __half g_W1T_h16[N1P_ * D_];               // single fp16 folded q,k weights
__device__ float g_W1v[D_ * NK_];
__device__ float g_Mout[H_ * 2 * F_ * D_];            // [h][p][x][o]
__device__ float g_aq[(size_t)B_ * H_ * F_ * N_];     // [bh][f][e]
__device__ float g_ak[(size_t)B_ * H_ * F_ * N_];
__device__ float g_attp[B_ * H_ * EQ_ * F_ * F_];
__device__ float g_att[B_ * H_ * F_ * F_];
__device__ float g_C[B_ * NK_ * D_];                  // [b][k][o]
__device__ __half g_DTh16[B_ * D_ * D_];              // [b][o][d] fp16 hi/lo
__device__ __half g_DTl16[B_ * D_ * D_];

// ---------------- helpers ----------------
__device__ __forceinline__ uint32_t smem_u32(const void* p) {
    uint32_t a;
    asm("{ .reg .u64 t; cvta.to.shared.u64 t, %1; cvt.u32.u64 %0, t; }" : "=r"(a) : "l"(p));
    return a;
}
__device__ __forceinline__ void ldsm_x4(uint32_t* r, uint32_t addr) {
    asm volatile("ldmatrix.sync.aligned.m8n8.x4.shared.b16 {%0,%1,%2,%3}, [%4];"
                 : "=r"(r[0]), "=r"(r[1]), "=r"(r[2]), "=r"(r[3]) : "r"(addr));
}
__device__ __forceinline__ void mma16816_f16(float* c, const uint32_t* a, const uint32_t* b) {
    asm volatile("mma.sync.aligned.m16n8k16.row.col.f32.f16.f16.f32 "
                 "{%0,%1,%2,%3}, {%4,%5,%6,%7}, {%8,%9}, {%0,%1,%2,%3};"
                 : "+f"(c[0]), "+f"(c[1]), "+f"(c[2]), "+f"(c[3])
                 : "r"(a[0]), "r"(a[1]), "r"(a[2]), "r"(a[3]), "r"(b[0]), "r"(b[1]));
}
#define FMA_F32X2(d, a, b) \
    asm("fma.rn.f32x2 %0, %1, %2, %0;" : "+l"(d) : "l"(a), "l"(b))
// swizzled offset within a [rows][64 x 16bit] tile (row = 128 bytes)
__device__ __forceinline__ uint32_t swz64(int row, int colbyte) {
    return (uint32_t)(row * 128 + (colbyte ^ ((row & 7) << 4)));
}
__device__ __forceinline__ void cp16(uint32_t dst, const void* src) {
    asm volatile("cp.async.cg.shared.global [%0], [%1], 16;" :: "r"(dst), "l"(src));
}
__device__ __forceinline__ void cp_commit() { asm volatile("cp.async.commit_group;"); }
__device__ __forceinline__ void cp_wait0() { asm volatile("cp.async.wait_group 0;" ::: "memory"); }
__device__ __forceinline__ void cp_wait1() { asm volatile("cp.async.wait_group 1;" ::: "memory"); }

// ---------------- merged prep ----------------
#define PREP_SPLIT  4096
#define PREP_W1     1088
#define PREP_W1V    520
#define PREP_MOUT   520
#define PREP_TOTAL  (PREP_SPLIT + PREP_W1 + PREP_W1V + PREP_MOUT)

__global__ void __launch_bounds__(256) prep_kernel(const float* __restrict__ X,
                                                   const float* __restrict__ w_qkv,
                                                   const float* __restrict__ w_out) {
    __shared__ float cs[128], sn[128];
    int tid = threadIdx.x;
    int blk = blockIdx.x;
    if (blk < PREP_SPLIT) {
        size_t i = (size_t)blk * 256 + tid;
        float4 v = ((const float4*)X)[i];
        __half2 p01 = __floats2half2_rn(v.x, v.y);
        __half2 p23 = __floats2half2_rn(v.z, v.w);
        ((uint2*)g_X16)[i] = make_uint2(*(uint32_t*)&p01, *(uint32_t*)&p23);
        return;
    }
    if (tid < 128) {
        float ang = (float)tid / 64.0f;
        cs[tid] = cospif(ang);
        sn[tid] = sinpif(ang);
    }
    __syncthreads();
    blk -= PREP_SPLIT;
    if (blk < PREP_W1) {
        int idx = blk * 256 + tid;
        int d = idx / N1P_, c = idx - d * N1P_;
        float acc = 0.f;
        if (c < N1_) {
            int region = (c >= 1040) ? 1 : 0;
            int cc = c - region * 1040;
            int hd = cc / 130;
            int u = cc - hd * 130;
            int f = u >> 1;
            const float* w = w_qkv + (size_t)d * 3072 + region * 1024 + hd * 128;
            if ((u & 1) == 0) {
                #pragma unroll 8
                for (int dd = 0; dd < 128; dd++) acc += w[dd] * cs[(f * dd) & 127];
            } else {
                #pragma unroll 8
                for (int dd = 0; dd < 128; dd++) acc -= w[dd] * sn[(f * dd) & 127];
            }
            acc *= SCALE_;
        }
        g_W1T_h16[c * 128 + d] = __float2half_rn(acc);
        return;
    }
    blk -= PREP_W1;
    if (blk < PREP_W1V) {
        int idx = blk * 256 + tid;
        int d = idx / NK_, k = idx - d * NK_;
        int hd = k / 130;
        int u = k - hd * 130;
        int f = u >> 1;
        const float* w = w_qkv + (size_t)d * 3072 + 2048 + hd * 128;
        float acc = 0.f;
        if ((u & 1) == 0) {
            #pragma unroll 8
            for (int dd = 0; dd < 128; dd++) acc += w[dd] * cs[(f * dd) & 127];
        } else {
            #pragma unroll 8
            for (int dd = 0; dd < 128; dd++) acc -= w[dd] * sn[(f * dd) & 127];
        }
        g_W1v[idx] = acc;
        return;
    }
    blk -= PREP_W1V;
    {
        int idx = blk * 256 + tid;
        int o = idx & 127;
        int r = idx >> 7;
        int x = r % 65;
        int hp = r / 65;
        int p = hp & 1, hd = hp >> 1;
        float acc = 0.f;
        if (p == 0) {
            #pragma unroll 8
            for (int t2 = 0; t2 < 128; t2++)
                acc += cs[(x * t2) & 127] * w_out[(size_t)(hd * 128 + t2) * 128 + o];
            acc *= ((x == 0 || x == 64) ? 1.0f : 2.0f) / 128.0f;
        } else if (x != 0 && x != 64) {
            #pragma unroll 8
            for (int t2 = 0; t2 < 128; t2++)
                acc -= sn[(x * t2) & 127] * w_out[(size_t)(hd * 128 + t2) * 128 + o];
            acc *= 2.0f / 128.0f;
        }
        g_Mout[idx] = acc;
    }
}

// ---------------- single-pass fp16 sweep over one resident [*x64] K-chunk ----------------
// warp grid 4x2 over 128x128; per k-step 6 ldsm feed 16 mma
__device__ __forceinline__ void mma_chunk64_1p(uint32_t sA, uint32_t sB,
                                               int lane, int wm, int wn, float c[2][8][4]) {
    #pragma unroll
    for (int ks = 0; ks < 4; ks++) {
        int colb = ks * 32 + (lane >> 4) * 16;
        int ar = wm * 32 + (lane & 15);
        uint32_t a[2][4];
        #pragma unroll
        for (int tm = 0; tm < 2; tm++)
            ldsm_x4(a[tm], sA + swz64(ar + tm * 16, colb));
        uint32_t b[8][2];
        #pragma unroll
        for (int ng = 0; ng < 4; ng++) {
            int n = wn * 64 + ng * 16 + (lane & 15);
            uint32_t q[4];
            ldsm_x4(q, sB + swz64(n, colb));
            b[2 * ng][0] = q[0]; b[2 * ng + 1][0] = q[1];
            b[2 * ng][1] = q[2]; b[2 * ng + 1][1] = q[3];
        }
        #pragma unroll
        for (int tm = 0; tm < 2; tm++)
            #pragma unroll
            for (int tn = 0; tn < 8; tn++)
                mma16816_f16(c[tm][tn], a[tm], b[tn]);
    }
}

// 2-pass fp16 sweep (A single, B hi/lo): per k-step 10 ldsm feed 32 mma
__device__ __forceinline__ void mma_chunk64_2p(uint32_t sA, uint32_t sBhi, uint32_t sBlo,
                                               int lane, int wm, int wn, float c[2][8][4]) {
    #pragma unroll
    for (int ks = 0; ks < 4; ks++) {
        int colb = ks * 32 + (lane >> 4) * 16;
        int ar = wm * 32 + (lane & 15);
        uint32_t a[2][4];
        #pragma unroll
        for (int tm = 0; tm < 2; tm++)
            ldsm_x4(a[tm], sA + swz64(ar + tm * 16, colb));
        uint32_t bhi[8][2];
        #pragma unroll
        for (int ng = 0; ng < 4; ng++) {
            int n = wn * 64 + ng * 16 + (lane & 15);
            uint32_t q[4];
            ldsm_x4(q, sBhi + swz64(n, colb));
            bhi[2 * ng][0] = q[0]; bhi[2 * ng + 1][0] = q[1];
            bhi[2 * ng][1] = q[2]; bhi[2 * ng + 1][1] = q[3];
        }
        #pragma unroll
        for (int tm = 0; tm < 2; tm++)
            #pragma unroll
            for (int tn = 0; tn < 8; tn++)
                mma16816_f16(c[tm][tn], a[tm], bhi[tn]);
        uint32_t blo[8][2];
        #pragma unroll
        for (int ng = 0; ng < 4; ng++) {
            int n = wn * 64 + ng * 16 + (lane & 15);
            uint32_t q[4];
            ldsm_x4(q, sBlo + swz64(n, colb));
            blo[2 * ng][0] = q[0]; blo[2 * ng + 1][0] = q[1];
            blo[2 * ng][1] = q[2]; blo[2 * ng + 1][1] = q[3];
        }
        #pragma unroll
        for (int tm = 0; tm < 2; tm++)
            #pragma unroll
            for (int tn = 0; tn < 8; tn++)
                mma16816_f16(c[tm][tn], a[tm], blo[tn]);
    }
}

// ---------------- GEMM1: single-pass fp16, m128 x n128, 256 thr, 2 CTAs/SM ----------------
// Stage 32KB: A 16K @0, B 16K @16384. 2 stages = 64 KB/CTA.
#define G1_STG 32768
__device__ __forceinline__ void g1_load(uint32_t sst, int bm, int bn, int k0, int tid) {
    #pragma unroll
    for (int u = tid; u < 1024; u += 256) {
        int r = u >> 3, cb = (u & 7) * 16;
        uint32_t d = swz64(r, cb);
        cp16(sst + d,         (const char*)g_X16 + ((size_t)(bm + r) * 128 + k0) * 2 + cb);
        cp16(sst + 16384 + d, (const char*)g_W1T_h16 + ((size_t)(bn + r) * 128 + k0) * 2 + cb);
    }
}

__global__ void __launch_bounds__(256, 2) gemm1_tc() {
    extern __shared__ char smem[];
    uint32_t sb = smem_u32(smem);
    int tid = threadIdx.x;
    int lane = tid & 31, wid = tid >> 5;
    int wm = wid & 3, wn = wid >> 2;      // 4 x 2 warps over 128 x 128
    int bm = blockIdx.y * 128, bn = blockIdx.x * 128;

    g1_load(sb, bm, bn, 0, tid);  cp_commit();
    g1_load(sb + G1_STG, bm, bn, 64, tid);  cp_commit();

    float c[2][8][4];
    #pragma unroll
    for (int i = 0; i < 2; i++)
        #pragma unroll
        for (int j = 0; j < 8; j++)
            #pragma unroll
            for (int k = 0; k < 4; k++) c[i][j][k] = 0.f;

    cp_wait1();
    __syncthreads();
    mma_chunk64_1p(sb, sb + 16384, lane, wm, wn, c);
    cp_wait0();
    __syncthreads();
    mma_chunk64_1p(sb + G1_STG, sb + G1_STG + 16384, lane, wm, wn, c);

    // epilogue: |q|,|k| into [bh][f][e] layout
    int g = lane >> 2, cp2 = (lane & 3) * 2;
    int bloc = (bm >> 11) * 8;               // b*8, constant per CTA
    #pragma unroll
    for (int tn = 0; tn < 8; tn++) {
        int col = bn + wn * 64 + tn * 8 + cp2;   // even
        if (col >= N1_) continue;
        int region = (col >= 1040) ? 1 : 0;
        int cc = col - region * 1040;
        int hd = cc / 130;
        int uu = cc - hd * 130;
        int f = uu >> 1;
        float* base = (region ? g_ak : g_aq) + ((size_t)(bloc + hd) * 65 + f) * 2048;
        #pragma unroll
        for (int tm = 0; tm < 2; tm++)
            #pragma unroll
            for (int hf = 0; hf < 2; hf++) {
                int e = (bm & 2047) + wm * 32 + tm * 16 + hf * 8 + g;
                float re = c[tm][tn][hf * 2], im = c[tm][tn][hf * 2 + 1];
                base[e] = sqrtf(re * re + im * im);
            }
    }
}

// ---------------- att partial: [f][e] layout, packed f32x2 FMA ----------------
__global__ void __launch_bounds__(256) att_partial_kernel() {
    __shared__ float aqs[65 * 66];
    __shared__ float aks[65 * 66];
    int bh = blockIdx.y;
    int chunk = blockIdx.x;
    int tid = threadIdx.x;
    int tx = tid & 15, ty = tid >> 4;
    int xs[5], ys[5];
    #pragma unroll
    for (int i = 0; i < 5; i++) {
        int x = tx + 16 * i; xs[i] = (x < 65) ? x : 0;
        int y = ty + 16 * i; ys[i] = (y < 65) ? y : 0;
    }
    unsigned long long acc2[5][5];
    #pragma unroll
    for (int i = 0; i < 5; i++)
        #pragma unroll
        for (int j = 0; j < 5; j++) acc2[i][j] = 0ull;

    const float* aqsrc = g_aq + (size_t)bh * 65 * 2048;
    const float* aksrc = g_ak + (size_t)bh * 65 * 2048;
    int ebase = chunk * (2048 / EQ_);
    for (int e0 = ebase; e0 < ebase + 2048 / EQ_; e0 += 64) {
        for (int idx = tid; idx < 4160; idx += 256) {
            int f = idx >> 6, r = idx & 63;        // coalesced: e fastest
            size_t gidx = (size_t)f * 2048 + e0 + r;
            aqs[f * 66 + r] = aqsrc[gidx];
            aks[f * 66 + r] = aksrc[gidx];
        }
        __syncthreads();
        #pragma unroll 4
        for (int e2 = 0; e2 < 64; e2 += 2) {
            unsigned long long av[5], bv[5];
            #pragma unroll
            for (int i = 0; i < 5; i++)
                av[i] = *(const unsigned long long*)&aqs[xs[i] * 66 + e2];
            #pragma unroll
            for (int j = 0; j < 5; j++)
                bv[j] = *(const unsigned long long*)&aks[ys[j] * 66 + e2];
            #pragma unroll
            for (int i = 0; i < 5; i++)
                #pragma unroll
                for (int j = 0; j < 5; j++)
                    FMA_F32X2(acc2[i][j], av[i], bv[j]);
        }
        __syncthreads();
    }
    float* dst = g_attp + (size_t)(bh * EQ_ + chunk) * 4225;
    #pragma unroll
    for (int i = 0; i < 5; i++) {
        int x = tx + 16 * i;
        if (x < 65)
            #pragma unroll
            for (int j = 0; j < 5; j++) {
                int y = ty + 16 * j;
                if (y < 65) {
                    float lo = __uint_as_float((uint32_t)(acc2[i][j] & 0xffffffffull));
                    float hi = __uint_as_float((uint32_t)(acc2[i][j] >> 32));
                    dst[x * 65 + y] = lo + hi;
                }
            }
    }
}

// ---------------- softmax: one warp per x-row ----------------
__global__ void __launch_bounds__(256) att_softmax_kernel() {
    int bh = blockIdx.y;
    int warp = threadIdx.x >> 5, lane = threadIdx.x & 31;
    int x = blockIdx.x * 8 + warp;
    if (x >= 65) return;
    const float* p0 = g_attp + (size_t)(bh * EQ_) * 4225 + x * 65;
    float v[3];
    float m = -3.4e38f;
    #pragma unroll
    for (int t = 0; t < 3; t++) {
        int y = lane + t * 32;
        float s = 0.f;
        if (y < 65) {
            #pragma unroll
            for (int q = 0; q < EQ_; q++) s += p0[q * 4225 + y];
        } else s = -3.4e38f;
        v[t] = s;
        m = fmaxf(m, s);
    }
    #pragma unroll
    for (int o = 16; o; o >>= 1) m = fmaxf(m, __shfl_xor_sync(0xffffffffu, m, o));
    float sum = 0.f;
    #pragma unroll
    for (int t = 0; t < 3; t++) {
        int y = lane + t * 32;
        if (y < 65) {
            v[t] = expf(v[t] - m);
            sum += v[t];
        }
    }
    #pragma unroll
    for (int o = 16; o; o >>= 1) sum += __shfl_xor_sync(0xffffffffu, sum, o);
    float inv = 1.0f / sum;
    float* dst = g_att + (size_t)bh * 4225 + x * 65;
    #pragma unroll
    for (int t = 0; t < 3; t++) {
        int y = lane + t * 32;
        if (y < 65) dst[y] = v[t] * inv;
    }
}

// ---------------- build C_b ----------------
__global__ void __launch_bounds__(256) build_c_kernel() {
    extern __shared__ float csm[];
    float* att_s = csm;
    float* mout_s = csm + 4225;
    int blk = blockIdx.x;                    // b*16 + h*2 + p
    int b = blk >> 4;
    int hp = blk & 15;
    int hd = hp >> 1, p = hp & 1;
    int tid = threadIdx.x;
    int bh = b * 8 + hd;
    for (int idx = tid; idx < 4225; idx += 256)
        att_s[idx] = g_att[(size_t)bh * 4225 + idx];
    for (int idx = tid; idx < 8320; idx += 256)
        mout_s[idx] = g_Mout[(size_t)hp * 8320 + idx];
    __syncthreads();
    for (int idx = tid; idx < 8320; idx += 256) {
        int o = idx / 65, y = idx - o * 65;
        float acc = 0.f;
        #pragma unroll 5
        for (int x = 0; x < 65; x++)
            acc += att_s[x * 65 + y] * mout_s[x * 128 + o];
        int k = hd * 130 + 2 * y + p;
        g_C[((size_t)b * NK_ + k) * 128 + o] = acc;
    }
}

// ---------------- build D_b = W1v @ C_b, split to fp16 hi/lo ----------------
__global__ void __launch_bounds__(256) build_d_kernel() {
    __shared__ float Wvs[128 * 65];
    __shared__ float Cs[65 * 32];
    int b = blockIdx.x;
    int o0 = blockIdx.y * 32;
    int tid = threadIdx.x;
    int ol = tid & 31, dg = tid >> 5;
    float acc[16];
    #pragma unroll
    for (int i = 0; i < 16; i++) acc[i] = 0.f;

    for (int k0 = 0; k0 < NK_; k0 += 65) {
        __syncthreads();
        for (int u = tid; u < 8320; u += 256) {
            int d = u / 65, kk = u - d * 65;
            Wvs[u] = g_W1v[(size_t)d * NK_ + k0 + kk];
        }
        for (int u = tid; u < 2080; u += 256) {
            int kk = u >> 5, oo = u & 31;
            Cs[u] = g_C[((size_t)b * NK_ + k0 + kk) * 128 + o0 + oo];
        }
        __syncthreads();
        #pragma unroll 5
        for (int kk = 0; kk < 65; kk++) {
            float cv = Cs[kk * 32 + ol];
            #pragma unroll
            for (int i = 0; i < 16; i++)
                acc[i] += Wvs[(dg + 8 * i) * 65 + kk] * cv;
        }
    }
    #pragma unroll
    for (int i = 0; i < 16; i++) {
        int d = dg + 8 * i;
        __half hi = __float2half_rn(acc[i]);
        size_t off = ((size_t)b * 128 + o0 + ol) * 128 + d;
        g_DTh16[off] = hi;
        g_DTl16[off] = __float2half_rn(acc[i] - __half2float(hi));
    }
}

// ---------------- final GEMM: fp16 2-pass, m128, 256 thr, 2 CTAs/SM ----------------
// per chunk: A 16K, Bhi 16K, Blo 16K. 2 chunks = 96 KB/CTA.
#define FG_A   0
#define FG_BHI 32768
#define FG_BLO 65536
#define FG_TOT 98304
__global__ void __launch_bounds__(256, 2) final_gemm(float* __restrict__ out,
                                                     const float* __restrict__ bias) {
    extern __shared__ char smem[];
    uint32_t sb = smem_u32(smem);
    int tid = threadIdx.x;
    int lane = tid & 31, wid = tid >> 5;
    int wm = wid & 3, wn = wid >> 2;     // 4 x 2 warps over 128 x 128
    int bm = blockIdx.x * 128;
    int b = bm >> 11;

    // two commit groups (K-chunk 0, then 1) so mma on ch0 overlaps ch1 load
    #pragma unroll
    for (int ch = 0; ch < 2; ch++) {
        #pragma unroll
        for (int u = tid; u < 1024; u += 256) {
            int r = u >> 3, cb = (u & 7) * 16;
            uint32_t d = ch * 16384 + swz64(r, cb);
            size_t asrc = (size_t)(bm + r) * 256 + ch * 128 + cb;
            size_t bsrc = ((size_t)(b * 128 + r)) * 256 + ch * 128 + cb;
            cp16(sb + FG_A + d, (const char*)g_X16 + asrc);
            cp16(sb + FG_BHI + d, (const char*)g_DTh16 + bsrc);
            cp16(sb + FG_BLO + d, (const char*)g_DTl16 + bsrc);
        }
        cp_commit();
    }

    float c[2][8][4];
    #pragma unroll
    for (int i = 0; i < 2; i++)
        #pragma unroll
        for (int j = 0; j < 8; j++)
            #pragma unroll
            for (int k = 0; k < 4; k++) c[i][j][k] = 0.f;

    cp_wait1();
    __syncthreads();
    mma_chunk64_2p(sb + FG_A, sb + FG_BHI, sb + FG_BLO, lane, wm, wn, c);
    cp_wait0();
    __syncthreads();
    mma_chunk64_2p(sb + FG_A + 16384, sb + FG_BHI + 16384, sb + FG_BLO + 16384,
                   lane, wm, wn, c);

    int g = lane >> 2, cp2 = (lane & 3) * 2;
    #pragma unroll
    for (int tm = 0; tm < 2; tm++)
        #pragma unroll
        for (int hf = 0; hf < 2; hf++) {
            size_t row = (size_t)bm + wm * 32 + tm * 16 + hf * 8 + g;
            float* dst = out + row * 128;
            #pragma unroll
            for (int tn = 0; tn < 8; tn++) {
                int col = wn * 64 + tn * 8 + cp2;
                float2 bv = *(const float2*)(bias + col);
                *(float2*)(dst + col) = make_float2(c[tm][tn][hf * 2] + bv.x,
                                                    c[tm][tn][hf * 2 + 1] + bv.y);
            }
        }
}

// ---------------- launch ----------------
extern "C" void kernel_launch(void* const* d_in, const int* in_sizes, int n_in,
                              void* d_out, int out_size) {
    const float* x     = (const float*)d_in[0];
    const float* w_qkv = (const float*)d_in[1];
    const float* w_out = (const float*)d_in[2];
    const float* b_out = (const float*)d_in[3];
    float* out = (float*)d_out;

    cudaFuncSetAttribute(gemm1_tc, cudaFuncAttributeMaxDynamicSharedMemorySize, 2 * G1_STG);
    cudaFuncSetAttribute(final_gemm, cudaFuncAttributeMaxDynamicSharedMemorySize, FG_TOT);
    cudaFuncSetAttribute(build_c_kernel, cudaFuncAttributeMaxDynamicSharedMemorySize,
                         (4225 + 8320) * 4);

    prep_kernel<<<PREP_TOTAL, 256>>>(x, w_qkv, w_out);
    gemm1_tc<<<dim3(N1P_ / 128, ROWS_ / 128), 256, 2 * G1_STG>>>();
    att_partial_kernel<<<dim3(EQ_, B_ * H_), 256>>>();
    att_softmax_kernel<<<dim3(9, B_ * H_), 256>>>();
    build_c_kernel<<<B_ * H_ * 2, 256, (4225 + 8320) * 4>>>();
    build_d_kernel<<<dim3(B_, 4), 256>>>();
    final_gemm<<<ROWS_ / 128, 256, FG_TOT>>>(out, b_out);
}